// round 1
// baseline (speedup 1.0000x reference)
#include <cuda_runtime.h>
#include <cuda_bf16.h>
#include <math.h>

// ---------------------------------------------------------------------------
// Problem constants
// ---------------------------------------------------------------------------
#define BATCH   2
#define SEQ     2048
#define HIDDEN  1024
#define Q_OUT   2048
#define KV_OUT  1024
#define HDIM    128
#define NQ      16
#define NKV     8
#define TOKENS  (BATCH*SEQ)          // 4096

// ---------------------------------------------------------------------------
// Scratch (device globals; no allocation allowed)
// ---------------------------------------------------------------------------
__device__ float g_q[TOKENS * Q_OUT];    // (token, h*128+d) after proj / norm+rope
__device__ float g_k[TOKENS * KV_OUT];
__device__ float g_v[TOKENS * KV_OUT];
__device__ float g_o[TOKENS * Q_OUT];    // attention output, (b,t,h,d)
__device__ float g_cosT[SEQ * 64];
__device__ float g_sinT[SEQ * 64];

// ---------------------------------------------------------------------------
// RoPE cos/sin table: emb[d] = t * 10000^{-(d%64)/64}
// ---------------------------------------------------------------------------
__global__ void rope_table_kernel() {
    int t = blockIdx.x;
    int j = threadIdx.x;   // 0..63
    float e = (float)j * (1.0f / 64.0f);
    float inv = exp2f(-e * 13.287712379549449f);  // log2(10000)
    float a = (float)t * inv;
    float s, c;
    sincosf(a, &s, &c);
    g_cosT[t * 64 + j] = c;
    g_sinT[t * 64 + j] = s;
}

// ---------------------------------------------------------------------------
// SGEMM: C[M,N] = A[M,K] @ B[K,N], all row-major, M%128==0, N%128==0, K%8==0
// 128x128 tile, BK=8, 256 threads, 8x8 per thread (2x2 blocks of 4x4)
// ---------------------------------------------------------------------------
__global__ __launch_bounds__(256) void sgemm_kernel(
    const float* __restrict__ A, const float* __restrict__ B,
    float* __restrict__ C, int M, int N, int K)
{
    __shared__ float As[8][128];   // transposed: As[k][m]
    __shared__ float Bs[8][128];   // Bs[k][n]

    int tid = threadIdx.x;
    int tx = tid & 15;
    int ty = tid >> 4;
    int row0 = blockIdx.y * 128;
    int col0 = blockIdx.x * 128;

    float acc[8][8];
#pragma unroll
    for (int i = 0; i < 8; i++)
#pragma unroll
        for (int j = 0; j < 8; j++) acc[i][j] = 0.0f;

    int arow = tid >> 1;            // 0..127
    int acol = (tid & 1) * 4;       // 0 or 4
    int brow = tid >> 5;            // 0..7
    int bcol = (tid & 31) * 4;      // 0..124

    const float* Ag = A + (size_t)(row0 + arow) * K + acol;
    const float* Bg = B + (size_t)brow * N + col0 + bcol;

    for (int k0 = 0; k0 < K; k0 += 8) {
        float4 a = *(const float4*)(Ag + k0);
        float4 b = *(const float4*)(Bg + (size_t)k0 * N);
        __syncthreads();
        As[acol + 0][arow] = a.x;
        As[acol + 1][arow] = a.y;
        As[acol + 2][arow] = a.z;
        As[acol + 3][arow] = a.w;
        *(float4*)&Bs[brow][bcol] = b;
        __syncthreads();

#pragma unroll
        for (int k = 0; k < 8; k++) {
            float4 a0 = *(float4*)&As[k][ty * 4];
            float4 a1 = *(float4*)&As[k][64 + ty * 4];
            float4 b0 = *(float4*)&Bs[k][tx * 4];
            float4 b1 = *(float4*)&Bs[k][64 + tx * 4];
            float ar[8] = {a0.x, a0.y, a0.z, a0.w, a1.x, a1.y, a1.z, a1.w};
            float br[8] = {b0.x, b0.y, b0.z, b0.w, b1.x, b1.y, b1.z, b1.w};
#pragma unroll
            for (int i = 0; i < 8; i++)
#pragma unroll
                for (int j = 0; j < 8; j++)
                    acc[i][j] = fmaf(ar[i], br[j], acc[i][j]);
        }
    }

#pragma unroll
    for (int bi = 0; bi < 2; bi++)
#pragma unroll
        for (int i = 0; i < 4; i++) {
            int r = row0 + bi * 64 + ty * 4 + i;
#pragma unroll
            for (int bj = 0; bj < 2; bj++) {
                float4 o;
                o.x = acc[bi * 4 + i][bj * 4 + 0];
                o.y = acc[bi * 4 + i][bj * 4 + 1];
                o.z = acc[bi * 4 + i][bj * 4 + 2];
                o.w = acc[bi * 4 + i][bj * 4 + 3];
                *(float4*)&C[(size_t)r * N + col0 + bj * 64 + tx * 4] = o;
            }
        }
}

// ---------------------------------------------------------------------------
// Per-head RMSNorm + RoPE (in-place on g_q / g_k)
// grid: (TOKENS, NQ+NKV), block 128
// ---------------------------------------------------------------------------
__global__ __launch_bounds__(128) void norm_rope_kernel(
    const float* __restrict__ qw, const float* __restrict__ kw)
{
    int token = blockIdx.x;
    int h = blockIdx.y;
    int d = threadIdx.x;
    bool is_q = (h < NQ);

    float* base = is_q ? (g_q + (size_t)token * Q_OUT + h * HDIM)
                       : (g_k + (size_t)token * KV_OUT + (h - NQ) * HDIM);
    const float* w = is_q ? qw : kw;

    float v = base[d];
    // sum of squares over 128
    float ss = v * v;
#pragma unroll
    for (int off = 16; off > 0; off >>= 1)
        ss += __shfl_xor_sync(0xffffffffu, ss, off);
    __shared__ float red[4];
    __shared__ float vals[128];
    int lane = d & 31, wid = d >> 5;
    if (lane == 0) red[wid] = ss;
    __syncthreads();
    float tot = red[0] + red[1] + red[2] + red[3];
    float r = rsqrtf(tot * (1.0f / 128.0f) + 1e-6f);
    float nv = v * r * w[d];
    vals[d] = nv;
    __syncthreads();

    int t = token & (SEQ - 1);
    float c = g_cosT[t * 64 + (d & 63)];
    float s = g_sinT[t * 64 + (d & 63)];
    float rot = (d < 64) ? -vals[d + 64] : vals[d - 64];
    base[d] = nv * c + rot * s;
}

// ---------------------------------------------------------------------------
// Flash attention (fp32, causal, GQA rep=2)
// grid: (SEQ/64, NQ, BATCH), block 256 (16x16)
// ---------------------------------------------------------------------------
#define QS_STR 132
#define PS_STR 72
#define FA_SMEM ((64*QS_STR + 64*QS_STR + 64*128 + 64*PS_STR) * 4)

__global__ __launch_bounds__(256) void flash_kernel(
    const float* __restrict__ Q, const float* __restrict__ K,
    const float* __restrict__ V, float* __restrict__ O)
{
    extern __shared__ float sm[];
    float* Qs = sm;                       // 64 x 132
    float* Ks = Qs + 64 * QS_STR;         // 64 x 132
    float* Vs = Ks + 64 * QS_STR;         // 64 x 128
    float* Ps = Vs + 64 * 128;            // 64 x 72

    int qt = blockIdx.x;
    int h  = blockIdx.y;
    int b  = blockIdx.z;
    int kvh = h >> 1;
    int q0 = qt * 64;

    int tid = threadIdx.x;
    int tx = tid & 15;
    int ty = tid >> 4;

    const float* qg = Q + ((size_t)(b * SEQ + q0) * NQ + h) * HDIM;   // row stride 2048
    // load Q tile (64 rows x 128)
    for (int idx = tid; idx < 64 * 32; idx += 256) {
        int r = idx >> 5, c = (idx & 31) << 2;
        *(float4*)(Qs + r * QS_STR + c) = *(const float4*)(qg + (size_t)r * Q_OUT + c);
    }

    float m_i[4], l_i[4], o[4][8];
#pragma unroll
    for (int i = 0; i < 4; i++) {
        m_i[i] = -1e30f; l_i[i] = 0.0f;
#pragma unroll
        for (int c = 0; c < 8; c++) o[i][c] = 0.0f;
    }
    __syncthreads();

    const float scale = 0.08838834764831845f;  // 1/sqrt(128)

    for (int kt = 0; kt <= qt; kt++) {
        int k0 = kt * 64;
        const float* kg = K + ((size_t)(b * SEQ + k0) * NKV + kvh) * HDIM;  // row stride 1024
        const float* vg = V + ((size_t)(b * SEQ + k0) * NKV + kvh) * HDIM;

        for (int idx = tid; idx < 64 * 32; idx += 256) {
            int r = idx >> 5, c = (idx & 31) << 2;
            float4 kv4 = *(const float4*)(kg + (size_t)r * KV_OUT + c);
            float4 vv4 = *(const float4*)(vg + (size_t)r * KV_OUT + c);
            *(float4*)(Ks + r * QS_STR + c) = kv4;
            *(float4*)(Vs + r * 128 + c) = vv4;
        }
        __syncthreads();

        // S = Q @ K^T (4x4 per thread)
        float s[4][4];
#pragma unroll
        for (int i = 0; i < 4; i++)
#pragma unroll
            for (int j = 0; j < 4; j++) s[i][j] = 0.0f;

        for (int k = 0; k < 128; k += 4) {
            float4 qv[4], kv[4];
#pragma unroll
            for (int i = 0; i < 4; i++)
                qv[i] = *(float4*)(Qs + (ty * 4 + i) * QS_STR + k);
#pragma unroll
            for (int j = 0; j < 4; j++)
                kv[j] = *(float4*)(Ks + (tx * 4 + j) * QS_STR + k);
#pragma unroll
            for (int i = 0; i < 4; i++)
#pragma unroll
                for (int j = 0; j < 4; j++) {
                    s[i][j] = fmaf(qv[i].x, kv[j].x, s[i][j]);
                    s[i][j] = fmaf(qv[i].y, kv[j].y, s[i][j]);
                    s[i][j] = fmaf(qv[i].z, kv[j].z, s[i][j]);
                    s[i][j] = fmaf(qv[i].w, kv[j].w, s[i][j]);
                }
        }

        // scale + causal mask (only diagonal tile)
        if (kt == qt) {
#pragma unroll
            for (int i = 0; i < 4; i++)
#pragma unroll
                for (int j = 0; j < 4; j++) {
                    bool masked = (tx * 4 + j) > (ty * 4 + i);
                    s[i][j] = masked ? -1e30f : s[i][j] * scale;
                }
        } else {
#pragma unroll
            for (int i = 0; i < 4; i++)
#pragma unroll
                for (int j = 0; j < 4; j++) s[i][j] *= scale;
        }

        // online softmax per row
#pragma unroll
        for (int i = 0; i < 4; i++) {
            float mt = fmaxf(fmaxf(s[i][0], s[i][1]), fmaxf(s[i][2], s[i][3]));
#pragma unroll
            for (int off = 8; off > 0; off >>= 1)
                mt = fmaxf(mt, __shfl_xor_sync(0xffffffffu, mt, off, 16));
            float m_new = fmaxf(m_i[i], mt);
            float corr = __expf(m_i[i] - m_new);
            m_i[i] = m_new;
            l_i[i] *= corr;
#pragma unroll
            for (int c = 0; c < 8; c++) o[i][c] *= corr;
            float rs = 0.0f;
#pragma unroll
            for (int j = 0; j < 4; j++) {
                float p = __expf(s[i][j] - m_new);
                s[i][j] = p;
                rs += p;
            }
#pragma unroll
            for (int off = 8; off > 0; off >>= 1)
                rs += __shfl_xor_sync(0xffffffffu, rs, off, 16);
            l_i[i] += rs;
        }

        // store P
#pragma unroll
        for (int i = 0; i < 4; i++) {
            float4 p4 = make_float4(s[i][0], s[i][1], s[i][2], s[i][3]);
            *(float4*)(Ps + (ty * 4 + i) * PS_STR + tx * 4) = p4;
        }
        __syncthreads();

        // O += P @ V
        for (int j = 0; j < 64; j++) {
            float4 va = *(float4*)(Vs + j * 128 + tx * 4);
            float4 vb = *(float4*)(Vs + j * 128 + 64 + tx * 4);
#pragma unroll
            for (int i = 0; i < 4; i++) {
                float p = Ps[(ty * 4 + i) * PS_STR + j];
                o[i][0] = fmaf(p, va.x, o[i][0]);
                o[i][1] = fmaf(p, va.y, o[i][1]);
                o[i][2] = fmaf(p, va.z, o[i][2]);
                o[i][3] = fmaf(p, va.w, o[i][3]);
                o[i][4] = fmaf(p, vb.x, o[i][4]);
                o[i][5] = fmaf(p, vb.y, o[i][5]);
                o[i][6] = fmaf(p, vb.z, o[i][6]);
                o[i][7] = fmaf(p, vb.w, o[i][7]);
            }
        }
        __syncthreads();
    }

    // epilogue
    float* og = O + ((size_t)(b * SEQ + q0) * NQ + h) * HDIM;
#pragma unroll
    for (int i = 0; i < 4; i++) {
        float inv = 1.0f / l_i[i];
        int r = ty * 4 + i;
        float4 oa = make_float4(o[i][0] * inv, o[i][1] * inv, o[i][2] * inv, o[i][3] * inv);
        float4 ob = make_float4(o[i][4] * inv, o[i][5] * inv, o[i][6] * inv, o[i][7] * inv);
        *(float4*)(og + (size_t)r * Q_OUT + tx * 4) = oa;
        *(float4*)(og + (size_t)r * Q_OUT + 64 + tx * 4) = ob;
    }
}

// ---------------------------------------------------------------------------
// Launch
// ---------------------------------------------------------------------------
extern "C" void kernel_launch(void* const* d_in, const int* in_sizes, int n_in,
                              void* d_out, int out_size)
{
    const float* x  = (const float*)d_in[0];
    const float* Wq = (const float*)d_in[1];
    const float* Wk = (const float*)d_in[2];
    const float* Wv = (const float*)d_in[3];
    const float* Wo = (const float*)d_in[4];
    const float* qw = (const float*)d_in[5];
    const float* kw = (const float*)d_in[6];
    float* out = (float*)d_out;

    float *pq, *pk, *pv, *po;
    cudaGetSymbolAddress((void**)&pq, g_q);
    cudaGetSymbolAddress((void**)&pk, g_k);
    cudaGetSymbolAddress((void**)&pv, g_v);
    cudaGetSymbolAddress((void**)&po, g_o);

    // RoPE tables
    rope_table_kernel<<<SEQ, 64>>>();

    // QKV projections
    sgemm_kernel<<<dim3(Q_OUT / 128, TOKENS / 128), 256>>>(x, Wq, pq, TOKENS, Q_OUT, HIDDEN);
    sgemm_kernel<<<dim3(KV_OUT / 128, TOKENS / 128), 256>>>(x, Wk, pk, TOKENS, KV_OUT, HIDDEN);
    sgemm_kernel<<<dim3(KV_OUT / 128, TOKENS / 128), 256>>>(x, Wv, pv, TOKENS, KV_OUT, HIDDEN);

    // RMSNorm + RoPE on q/k
    norm_rope_kernel<<<dim3(TOKENS, NQ + NKV), 128>>>(qw, kw);

    // Flash attention
    cudaFuncSetAttribute(flash_kernel, cudaFuncAttributeMaxDynamicSharedMemorySize, FA_SMEM);
    flash_kernel<<<dim3(SEQ / 64, NQ, BATCH), 256, FA_SMEM>>>(pq, pk, pv, po);

    // Output projection
    sgemm_kernel<<<dim3(HIDDEN / 128, TOKENS / 128), 256>>>(po, Wo, out, TOKENS, HIDDEN, Q_OUT);
}

// round 2
// speedup vs baseline: 2.0528x; 2.0528x over previous
#include <cuda_runtime.h>
#include <cuda_bf16.h>
#include <math.h>

// ---------------------------------------------------------------------------
// Problem constants
// ---------------------------------------------------------------------------
#define BATCH   2
#define SEQ     2048
#define HIDDEN  1024
#define Q_OUT   2048
#define KV_OUT  1024
#define HDIM    128
#define NQ      16
#define NKV     8
#define TOKENS  (BATCH*SEQ)          // 4096

// ---------------------------------------------------------------------------
// Scratch (device globals; no allocation allowed)
// ---------------------------------------------------------------------------
__device__ float g_q[TOKENS * Q_OUT];    // (token, h*128+d) after proj / norm+rope
__device__ float g_k[TOKENS * KV_OUT];
__device__ float g_v[TOKENS * KV_OUT];
__device__ float g_o[TOKENS * Q_OUT];    // attention output, (b,t,h,d)
__device__ float g_cosT[SEQ * 64];
__device__ float g_sinT[SEQ * 64];

// ---------------------------------------------------------------------------
// tf32 helpers
// ---------------------------------------------------------------------------
__device__ __forceinline__ unsigned cvt_tf32(float f) {
    unsigned u;
    asm("cvt.rna.tf32.f32 %0, %1;" : "=r"(u) : "f"(f));
    return u;
}

__device__ __forceinline__ void mma_tf32(float* c, const unsigned* a,
                                         unsigned b0, unsigned b1) {
    asm("mma.sync.aligned.m16n8k8.row.col.f32.tf32.tf32.f32 "
        "{%0,%1,%2,%3}, {%4,%5,%6,%7}, {%8,%9}, {%0,%1,%2,%3};"
        : "+f"(c[0]), "+f"(c[1]), "+f"(c[2]), "+f"(c[3])
        : "r"(a[0]), "r"(a[1]), "r"(a[2]), "r"(a[3]), "r"(b0), "r"(b1));
}

// ---------------------------------------------------------------------------
// RoPE cos/sin table
// ---------------------------------------------------------------------------
__global__ void rope_table_kernel() {
    int t = blockIdx.x;
    int j = threadIdx.x;   // 0..63
    float e = (float)j * (1.0f / 64.0f);
    float inv = exp2f(-e * 13.287712379549449f);  // log2(10000)
    float a = (float)t * inv;
    float s, c;
    sincosf(a, &s, &c);
    g_cosT[t * 64 + j] = c;
    g_sinT[t * 64 + j] = s;
}

// ---------------------------------------------------------------------------
// Fused QKV SGEMM: one launch covering Wq/Wk/Wv (fp32)
// 128x128 tile, BK=8, 256 threads, 8x8 per thread
// grid: (32, TOKENS/128): bx<16 -> Wq, bx<24 -> Wk, else Wv. K=1024.
// ---------------------------------------------------------------------------
__global__ __launch_bounds__(256) void qkv_gemm_kernel(
    const float* __restrict__ A,
    const float* __restrict__ Wq, const float* __restrict__ Wk,
    const float* __restrict__ Wv)
{
    __shared__ float As[8][128];
    __shared__ float Bs[8][128];

    int bx = blockIdx.x;
    const float* B;
    float* C;
    int N, col0;
    if (bx < 16)      { B = Wq; C = g_q; N = Q_OUT;  col0 = bx * 128; }
    else if (bx < 24) { B = Wk; C = g_k; N = KV_OUT; col0 = (bx - 16) * 128; }
    else              { B = Wv; C = g_v; N = KV_OUT; col0 = (bx - 24) * 128; }
    const int K = HIDDEN;

    int tid = threadIdx.x;
    int tx = tid & 15;
    int ty = tid >> 4;
    int row0 = blockIdx.y * 128;

    float acc[8][8];
#pragma unroll
    for (int i = 0; i < 8; i++)
#pragma unroll
        for (int j = 0; j < 8; j++) acc[i][j] = 0.0f;

    int arow = tid >> 1;
    int acol = (tid & 1) * 4;
    int brow = tid >> 5;
    int bcol = (tid & 31) * 4;

    const float* Ag = A + (size_t)(row0 + arow) * K + acol;
    const float* Bg = B + (size_t)brow * N + col0 + bcol;

    for (int k0 = 0; k0 < K; k0 += 8) {
        float4 a = *(const float4*)(Ag + k0);
        float4 b = *(const float4*)(Bg + (size_t)k0 * N);
        __syncthreads();
        As[acol + 0][arow] = a.x;
        As[acol + 1][arow] = a.y;
        As[acol + 2][arow] = a.z;
        As[acol + 3][arow] = a.w;
        *(float4*)&Bs[brow][bcol] = b;
        __syncthreads();

#pragma unroll
        for (int k = 0; k < 8; k++) {
            float4 a0 = *(float4*)&As[k][ty * 4];
            float4 a1 = *(float4*)&As[k][64 + ty * 4];
            float4 b0 = *(float4*)&Bs[k][tx * 4];
            float4 b1 = *(float4*)&Bs[k][64 + tx * 4];
            float ar[8] = {a0.x, a0.y, a0.z, a0.w, a1.x, a1.y, a1.z, a1.w};
            float br[8] = {b0.x, b0.y, b0.z, b0.w, b1.x, b1.y, b1.z, b1.w};
#pragma unroll
            for (int i = 0; i < 8; i++)
#pragma unroll
                for (int j = 0; j < 8; j++)
                    acc[i][j] = fmaf(ar[i], br[j], acc[i][j]);
        }
    }

#pragma unroll
    for (int bi = 0; bi < 2; bi++)
#pragma unroll
        for (int i = 0; i < 4; i++) {
            int r = row0 + bi * 64 + ty * 4 + i;
#pragma unroll
            for (int bj = 0; bj < 2; bj++) {
                float4 o;
                o.x = acc[bi * 4 + i][bj * 4 + 0];
                o.y = acc[bi * 4 + i][bj * 4 + 1];
                o.z = acc[bi * 4 + i][bj * 4 + 2];
                o.w = acc[bi * 4 + i][bj * 4 + 3];
                *(float4*)&C[(size_t)r * N + col0 + bj * 64 + tx * 4] = o;
            }
        }
}

// ---------------------------------------------------------------------------
// Plain SGEMM for Wo (fp32)
// ---------------------------------------------------------------------------
__global__ __launch_bounds__(256) void sgemm_kernel(
    const float* __restrict__ A, const float* __restrict__ B,
    float* __restrict__ C, int M, int N, int K)
{
    __shared__ float As[8][128];
    __shared__ float Bs[8][128];

    int tid = threadIdx.x;
    int tx = tid & 15;
    int ty = tid >> 4;
    int row0 = blockIdx.y * 128;
    int col0 = blockIdx.x * 128;

    float acc[8][8];
#pragma unroll
    for (int i = 0; i < 8; i++)
#pragma unroll
        for (int j = 0; j < 8; j++) acc[i][j] = 0.0f;

    int arow = tid >> 1;
    int acol = (tid & 1) * 4;
    int brow = tid >> 5;
    int bcol = (tid & 31) * 4;

    const float* Ag = A + (size_t)(row0 + arow) * K + acol;
    const float* Bg = B + (size_t)brow * N + col0 + bcol;

    for (int k0 = 0; k0 < K; k0 += 8) {
        float4 a = *(const float4*)(Ag + k0);
        float4 b = *(const float4*)(Bg + (size_t)k0 * N);
        __syncthreads();
        As[acol + 0][arow] = a.x;
        As[acol + 1][arow] = a.y;
        As[acol + 2][arow] = a.z;
        As[acol + 3][arow] = a.w;
        *(float4*)&Bs[brow][bcol] = b;
        __syncthreads();

#pragma unroll
        for (int k = 0; k < 8; k++) {
            float4 a0 = *(float4*)&As[k][ty * 4];
            float4 a1 = *(float4*)&As[k][64 + ty * 4];
            float4 b0 = *(float4*)&Bs[k][tx * 4];
            float4 b1 = *(float4*)&Bs[k][64 + tx * 4];
            float ar[8] = {a0.x, a0.y, a0.z, a0.w, a1.x, a1.y, a1.z, a1.w};
            float br[8] = {b0.x, b0.y, b0.z, b0.w, b1.x, b1.y, b1.z, b1.w};
#pragma unroll
            for (int i = 0; i < 8; i++)
#pragma unroll
                for (int j = 0; j < 8; j++)
                    acc[i][j] = fmaf(ar[i], br[j], acc[i][j]);
        }
    }

#pragma unroll
    for (int bi = 0; bi < 2; bi++)
#pragma unroll
        for (int i = 0; i < 4; i++) {
            int r = row0 + bi * 64 + ty * 4 + i;
#pragma unroll
            for (int bj = 0; bj < 2; bj++) {
                float4 o;
                o.x = acc[bi * 4 + i][bj * 4 + 0];
                o.y = acc[bi * 4 + i][bj * 4 + 1];
                o.z = acc[bi * 4 + i][bj * 4 + 2];
                o.w = acc[bi * 4 + i][bj * 4 + 3];
                *(float4*)&C[(size_t)r * N + col0 + bj * 64 + tx * 4] = o;
            }
        }
}

// ---------------------------------------------------------------------------
// Per-head RMSNorm + RoPE (in-place on g_q / g_k)
// ---------------------------------------------------------------------------
__global__ __launch_bounds__(128) void norm_rope_kernel(
    const float* __restrict__ qw, const float* __restrict__ kw)
{
    int token = blockIdx.x;
    int h = blockIdx.y;
    int d = threadIdx.x;
    bool is_q = (h < NQ);

    float* base = is_q ? (g_q + (size_t)token * Q_OUT + h * HDIM)
                       : (g_k + (size_t)token * KV_OUT + (h - NQ) * HDIM);
    const float* w = is_q ? qw : kw;

    float v = base[d];
    float ss = v * v;
#pragma unroll
    for (int off = 16; off > 0; off >>= 1)
        ss += __shfl_xor_sync(0xffffffffu, ss, off);
    __shared__ float red[4];
    __shared__ float vals[128];
    int lane = d & 31, wid = d >> 5;
    if (lane == 0) red[wid] = ss;
    __syncthreads();
    float tot = red[0] + red[1] + red[2] + red[3];
    float r = rsqrtf(tot * (1.0f / 128.0f) + 1e-6f);
    float nv = v * r * w[d];
    vals[d] = nv;
    __syncthreads();

    int t = token & (SEQ - 1);
    float c = g_cosT[t * 64 + (d & 63)];
    float s = g_sinT[t * 64 + (d & 63)];
    float rot = (d < 64) ? -vals[d + 64] : vals[d - 64];
    base[d] = nv * c + rot * s;
}

// ---------------------------------------------------------------------------
// Flash attention, tf32 mma.sync, causal, GQA rep=2
// Q tile 128 rows, K/V tile 64 keys. 8 warps x 16 rows.
// grid: (SEQ/128, NQ, BATCH), block 256
// ---------------------------------------------------------------------------
#define KS_STR 132
#define VS_STR 136
#define PS_STR 68
#define FA2_SMEM ((64*KS_STR + 64*VS_STR + 128*PS_STR) * 4)

__global__ __launch_bounds__(256, 1) void flash_tf32_kernel(
    const float* __restrict__ Q, const float* __restrict__ K,
    const float* __restrict__ V, float* __restrict__ O)
{
    extern __shared__ unsigned smu[];
    unsigned* Ks = smu;                    // [64][132] tf32
    unsigned* Vs = Ks + 64 * KS_STR;       // [64][136] tf32
    unsigned* Ps = Vs + 64 * VS_STR;       // [128][68] tf32

    int qt = gridDim.x - 1 - blockIdx.x;   // big tiles first
    int h  = blockIdx.y;
    int b  = blockIdx.z;
    int kvh = h >> 1;
    int q0 = qt * 128;

    int tid = threadIdx.x;
    int w = tid >> 5;
    int lane = tid & 31;
    int g = lane >> 2;      // groupID 0..7
    int t = lane & 3;       // thread-in-group 0..3

    int row0 = w * 16 + g;          // warp-local S row of c0/c1
    int row1 = row0 + 8;            // row of c2/c3
    int qrow0 = q0 + row0;          // global query index
    int qrow1 = q0 + row1;

    // --- Q fragments in registers (pre-scaled, tf32) ---
    unsigned qf[16][4];
    {
        const float scale = 0.08838834764831845f;  // 1/sqrt(128)
        const float* qb0 = Q + ((size_t)(b * SEQ + qrow0) * NQ + h) * HDIM;
        const float* qb1 = Q + ((size_t)(b * SEQ + qrow1) * NQ + h) * HDIM;
#pragma unroll
        for (int ks = 0; ks < 16; ks++) {
            int c0 = ks * 8 + t;
            qf[ks][0] = cvt_tf32(qb0[c0] * scale);
            qf[ks][1] = cvt_tf32(qb1[c0] * scale);
            qf[ks][2] = cvt_tf32(qb0[c0 + 4] * scale);
            qf[ks][3] = cvt_tf32(qb1[c0 + 4] * scale);
        }
    }

    float of[16][4];
#pragma unroll
    for (int j = 0; j < 16; j++)
#pragma unroll
        for (int c = 0; c < 4; c++) of[j][c] = 0.0f;
    float m0 = -1e30f, m1 = -1e30f, l0 = 0.0f, l1 = 0.0f;

    int nkt = 2 * qt + 2;

    for (int kt = 0; kt < nkt; kt++) {
        int k0 = kt * 64;
        __syncthreads();
        // --- load K/V tile, convert to tf32 ---
        {
            const float* kg = K + ((size_t)(b * SEQ + k0) * NKV + kvh) * HDIM;
            const float* vg = V + ((size_t)(b * SEQ + k0) * NKV + kvh) * HDIM;
#pragma unroll
            for (int it = 0; it < 8; it++) {
                int idx = tid + it * 256;
                int r = idx >> 5, c = (idx & 31) * 4;
                float4 k4 = *(const float4*)(kg + (size_t)r * KV_OUT + c);
                float4 v4 = *(const float4*)(vg + (size_t)r * KV_OUT + c);
                uint4 ku = make_uint4(cvt_tf32(k4.x), cvt_tf32(k4.y),
                                      cvt_tf32(k4.z), cvt_tf32(k4.w));
                uint4 vu = make_uint4(cvt_tf32(v4.x), cvt_tf32(v4.y),
                                      cvt_tf32(v4.z), cvt_tf32(v4.w));
                *(uint4*)(Ks + r * KS_STR + c) = ku;
                *(uint4*)(Vs + r * VS_STR + c) = vu;
            }
        }
        __syncthreads();

        // skip fully-masked warps (all keys in tile > all rows of this warp)
        if (k0 > q0 + w * 16 + 15) continue;

        // --- S = Q @ K^T ---
        float sf[8][4];
#pragma unroll
        for (int j = 0; j < 8; j++)
#pragma unroll
            for (int c = 0; c < 4; c++) sf[j][c] = 0.0f;

#pragma unroll
        for (int ks = 0; ks < 16; ks++) {
#pragma unroll
            for (int j = 0; j < 8; j++) {
                const unsigned* kr = Ks + (j * 8 + g) * KS_STR + ks * 8 + t;
                mma_tf32(sf[j], qf[ks], kr[0], kr[4]);
            }
        }

        // --- causal mask (only last two k-tiles can cross the diagonal) ---
        if (kt >= nkt - 2) {
#pragma unroll
            for (int j = 0; j < 8; j++) {
                int kg0 = k0 + j * 8 + 2 * t;
                if (kg0 > qrow0)     sf[j][0] = -1e30f;
                if (kg0 + 1 > qrow0) sf[j][1] = -1e30f;
                if (kg0 > qrow1)     sf[j][2] = -1e30f;
                if (kg0 + 1 > qrow1) sf[j][3] = -1e30f;
            }
        }

        // --- online softmax ---
        float mt0 = -1e30f, mt1 = -1e30f;
#pragma unroll
        for (int j = 0; j < 8; j++) {
            mt0 = fmaxf(mt0, fmaxf(sf[j][0], sf[j][1]));
            mt1 = fmaxf(mt1, fmaxf(sf[j][2], sf[j][3]));
        }
        mt0 = fmaxf(mt0, __shfl_xor_sync(0xffffffffu, mt0, 1));
        mt0 = fmaxf(mt0, __shfl_xor_sync(0xffffffffu, mt0, 2));
        mt1 = fmaxf(mt1, __shfl_xor_sync(0xffffffffu, mt1, 1));
        mt1 = fmaxf(mt1, __shfl_xor_sync(0xffffffffu, mt1, 2));

        float mn0 = fmaxf(m0, mt0), mn1 = fmaxf(m1, mt1);
        float corr0 = __expf(m0 - mn0), corr1 = __expf(m1 - mn1);
        m0 = mn0; m1 = mn1;

        float rs0 = 0.0f, rs1 = 0.0f;
#pragma unroll
        for (int j = 0; j < 8; j++) {
            sf[j][0] = __expf(sf[j][0] - mn0);
            sf[j][1] = __expf(sf[j][1] - mn0);
            sf[j][2] = __expf(sf[j][2] - mn1);
            sf[j][3] = __expf(sf[j][3] - mn1);
            rs0 += sf[j][0] + sf[j][1];
            rs1 += sf[j][2] + sf[j][3];
        }
        rs0 += __shfl_xor_sync(0xffffffffu, rs0, 1);
        rs0 += __shfl_xor_sync(0xffffffffu, rs0, 2);
        rs1 += __shfl_xor_sync(0xffffffffu, rs1, 1);
        rs1 += __shfl_xor_sync(0xffffffffu, rs1, 2);
        l0 = l0 * corr0 + rs0;
        l1 = l1 * corr1 + rs1;

#pragma unroll
        for (int j = 0; j < 16; j++) {
            of[j][0] *= corr0; of[j][1] *= corr0;
            of[j][2] *= corr1; of[j][3] *= corr1;
        }

        // --- store P (tf32) to warp-private smem rows ---
#pragma unroll
        for (int j = 0; j < 8; j++) {
            uint2 p01 = make_uint2(cvt_tf32(sf[j][0]), cvt_tf32(sf[j][1]));
            uint2 p23 = make_uint2(cvt_tf32(sf[j][2]), cvt_tf32(sf[j][3]));
            *(uint2*)(Ps + row0 * PS_STR + j * 8 + 2 * t) = p01;
            *(uint2*)(Ps + row1 * PS_STR + j * 8 + 2 * t) = p23;
        }
        __syncwarp();

        // --- O += P @ V ---
#pragma unroll
        for (int ks = 0; ks < 8; ks++) {
            unsigned pa[4];
            pa[0] = Ps[row0 * PS_STR + ks * 8 + t];
            pa[1] = Ps[row1 * PS_STR + ks * 8 + t];
            pa[2] = Ps[row0 * PS_STR + ks * 8 + t + 4];
            pa[3] = Ps[row1 * PS_STR + ks * 8 + t + 4];
#pragma unroll
            for (int j = 0; j < 16; j++) {
                unsigned b0 = Vs[(ks * 8 + t) * VS_STR + j * 8 + g];
                unsigned b1 = Vs[(ks * 8 + t + 4) * VS_STR + j * 8 + g];
                mma_tf32(of[j], pa, b0, b1);
            }
        }
    }

    // --- epilogue ---
    float inv0 = 1.0f / l0, inv1 = 1.0f / l1;
    float* og0 = O + ((size_t)(b * SEQ + qrow0) * NQ + h) * HDIM;
    float* og1 = O + ((size_t)(b * SEQ + qrow1) * NQ + h) * HDIM;
#pragma unroll
    for (int j = 0; j < 16; j++) {
        float2 v0 = make_float2(of[j][0] * inv0, of[j][1] * inv0);
        float2 v1 = make_float2(of[j][2] * inv1, of[j][3] * inv1);
        *(float2*)(og0 + j * 8 + 2 * t) = v0;
        *(float2*)(og1 + j * 8 + 2 * t) = v1;
    }
}

// ---------------------------------------------------------------------------
// Launch
// ---------------------------------------------------------------------------
extern "C" void kernel_launch(void* const* d_in, const int* in_sizes, int n_in,
                              void* d_out, int out_size)
{
    const float* x  = (const float*)d_in[0];
    const float* Wq = (const float*)d_in[1];
    const float* Wk = (const float*)d_in[2];
    const float* Wv = (const float*)d_in[3];
    const float* Wo = (const float*)d_in[4];
    const float* qw = (const float*)d_in[5];
    const float* kw = (const float*)d_in[6];
    float* out = (float*)d_out;

    float *pq, *pk, *pv, *po;
    cudaGetSymbolAddress((void**)&pq, g_q);
    cudaGetSymbolAddress((void**)&pk, g_k);
    cudaGetSymbolAddress((void**)&pv, g_v);
    cudaGetSymbolAddress((void**)&po, g_o);

    // RoPE tables
    rope_table_kernel<<<SEQ, 64>>>();

    // Fused QKV projections (fp32)
    qkv_gemm_kernel<<<dim3(32, TOKENS / 128), 256>>>(x, Wq, Wk, Wv);

    // RMSNorm + RoPE on q/k
    norm_rope_kernel<<<dim3(TOKENS, NQ + NKV), 128>>>(qw, kw);

    // Flash attention (tf32 tensor cores)
    cudaFuncSetAttribute(flash_tf32_kernel,
                         cudaFuncAttributeMaxDynamicSharedMemorySize, FA2_SMEM);
    flash_tf32_kernel<<<dim3(SEQ / 128, NQ, BATCH), 256, FA2_SMEM>>>(pq, pk, pv, po);

    // Output projection (fp32)
    sgemm_kernel<<<dim3(HIDDEN / 128, TOKENS / 128), 256>>>(po, Wo, out, TOKENS, HIDDEN, Q_OUT);
}

// round 3
// speedup vs baseline: 4.3658x; 2.1267x over previous
#include <cuda_runtime.h>
#include <cuda_bf16.h>
#include <math.h>

// ---------------------------------------------------------------------------
// Problem constants
// ---------------------------------------------------------------------------
#define BATCH   2
#define SEQ     2048
#define HIDDEN  1024
#define Q_OUT   2048
#define KV_OUT  1024
#define HDIM    128
#define NQ      16
#define NKV     8
#define TOKENS  (BATCH*SEQ)          // 4096

// ---------------------------------------------------------------------------
// Scratch (device globals; no allocation allowed)
// ---------------------------------------------------------------------------
__device__ float g_q[TOKENS * Q_OUT];    // (token, h*128+d) after norm+rope
__device__ float g_k[TOKENS * KV_OUT];
__device__ float g_v[TOKENS * KV_OUT];
__device__ float g_o[TOKENS * Q_OUT];    // attention output, (b,t,h,d)
__device__ float g_cosT[SEQ * 64];
__device__ float g_sinT[SEQ * 64];

// ---------------------------------------------------------------------------
// tf32 helpers
// ---------------------------------------------------------------------------
__device__ __forceinline__ unsigned cvt_tf32(float f) {
    unsigned u;
    asm("cvt.rna.tf32.f32 %0, %1;" : "=r"(u) : "f"(f));
    return u;
}

__device__ __forceinline__ void mma_tf32(float* c, const unsigned* a,
                                         unsigned b0, unsigned b1) {
    asm("mma.sync.aligned.m16n8k8.row.col.f32.tf32.tf32.f32 "
        "{%0,%1,%2,%3}, {%4,%5,%6,%7}, {%8,%9}, {%0,%1,%2,%3};"
        : "+f"(c[0]), "+f"(c[1]), "+f"(c[2]), "+f"(c[3])
        : "r"(a[0]), "r"(a[1]), "r"(a[2]), "r"(a[3]), "r"(b0), "r"(b1));
}

// ---------------------------------------------------------------------------
// RoPE cos/sin table
// ---------------------------------------------------------------------------
__global__ void rope_table_kernel() {
    int t = blockIdx.x;
    int j = threadIdx.x;   // 0..63
    float e = (float)j * (1.0f / 64.0f);
    float inv = exp2f(-e * 13.287712379549449f);  // log2(10000)
    float a = (float)t * inv;
    float s, c;
    sincosf(a, &s, &c);
    g_cosT[t * 64 + j] = c;
    g_sinT[t * 64 + j] = s;
}

// ---------------------------------------------------------------------------
// tf32 GEMM core: 128x128 block tile, BK=16, 256 threads (8 warps, 2m x 4n)
// Warp tile: 64 rows x 32 cols, cols = wn + {0,8,64,72} (closed under +-64).
// As: [m][k] stride 20 (frag reads 20g+t conflict-free)
// Bs: [k][n] stride 136 (frag reads 8t+g conflict-free)
// ---------------------------------------------------------------------------
#define AS_STR 20
#define BS_STR 136

__device__ __forceinline__ void gemm_core_tf32(
    const float* __restrict__ A, const float* __restrict__ B,
    int K, int ldb, int row0, int col0,
    unsigned* As, unsigned* Bs, float acc[4][4][4])
{
    int tid = threadIdx.x;
    int lane = tid & 31;
    int wi = tid >> 5;
    int g = lane >> 2;
    int t = lane & 3;
    int warp_m = (wi & 1) * 64;
    int warp_n = (wi >> 1) * 16;

    for (int k0 = 0; k0 < K; k0 += 16) {
        float4 av[2], bv[2];
#pragma unroll
        for (int it = 0; it < 2; it++) {
            int idx = tid + it * 256;
            int m  = idx >> 2, kq = (idx & 3) * 4;
            av[it] = *(const float4*)(A + (size_t)(row0 + m) * K + k0 + kq);
            int kb = idx >> 5, nq = (idx & 31) * 4;
            bv[it] = *(const float4*)(B + (size_t)(k0 + kb) * ldb + col0 + nq);
        }
        __syncthreads();
#pragma unroll
        for (int it = 0; it < 2; it++) {
            int idx = tid + it * 256;
            int m  = idx >> 2, kq = (idx & 3) * 4;
            uint4 au = make_uint4(cvt_tf32(av[it].x), cvt_tf32(av[it].y),
                                  cvt_tf32(av[it].z), cvt_tf32(av[it].w));
            *(uint4*)(As + m * AS_STR + kq) = au;
            int kb = idx >> 5, nq = (idx & 31) * 4;
            uint4 bu = make_uint4(cvt_tf32(bv[it].x), cvt_tf32(bv[it].y),
                                  cvt_tf32(bv[it].z), cvt_tf32(bv[it].w));
            *(uint4*)(Bs + kb * BS_STR + nq) = bu;
        }
        __syncthreads();

#pragma unroll
        for (int ks = 0; ks < 2; ks++) {
            unsigned af[4][4], bf[4][2];
#pragma unroll
            for (int mi = 0; mi < 4; mi++) {
                int mb = warp_m + mi * 16;
                af[mi][0] = As[(mb + g) * AS_STR + ks * 8 + t];
                af[mi][1] = As[(mb + g + 8) * AS_STR + ks * 8 + t];
                af[mi][2] = As[(mb + g) * AS_STR + ks * 8 + t + 4];
                af[mi][3] = As[(mb + g + 8) * AS_STR + ks * 8 + t + 4];
            }
#pragma unroll
            for (int nj = 0; nj < 4; nj++) {
                int noff = (nj & 1) * 8 + (nj >> 1) * 64;   // {0,8,64,72}
                int cb = warp_n + noff + g;
                bf[nj][0] = Bs[(ks * 8 + t) * BS_STR + cb];
                bf[nj][1] = Bs[(ks * 8 + t + 4) * BS_STR + cb];
            }
#pragma unroll
            for (int mi = 0; mi < 4; mi++)
#pragma unroll
                for (int nj = 0; nj < 4; nj++)
                    mma_tf32(acc[mi][nj], af[mi], bf[nj][0], bf[nj][1]);
        }
    }
}

// ---------------------------------------------------------------------------
// Fused QKV GEMM (tf32) + per-head RMSNorm + RoPE epilogue for Q/K
// grid (32, TOKENS/128): bx<16 -> Wq->g_q(norm), bx<24 -> Wk->g_k(norm),
// else Wv->g_v plain. N-tile (128 cols) == one head.
// ---------------------------------------------------------------------------
__global__ __launch_bounds__(256, 2) void qkv_tf32_kernel(
    const float* __restrict__ x,
    const float* __restrict__ Wq, const float* __restrict__ Wk,
    const float* __restrict__ Wv,
    const float* __restrict__ qw, const float* __restrict__ kw)
{
    __shared__ unsigned As[128 * AS_STR];
    __shared__ unsigned Bs[16 * BS_STR];
    __shared__ float sred[128][4];

    int bx = blockIdx.x;
    const float* B; float* C; const float* w; int ldb, col0, donorm;
    if (bx < 16)      { B = Wq; C = g_q; ldb = Q_OUT;  col0 = bx * 128;        donorm = 1; w = qw; }
    else if (bx < 24) { B = Wk; C = g_k; ldb = KV_OUT; col0 = (bx - 16) * 128; donorm = 1; w = kw; }
    else              { B = Wv; C = g_v; ldb = KV_OUT; col0 = (bx - 24) * 128; donorm = 0; w = qw; }

    int row0 = blockIdx.y * 128;

    float acc[4][4][4];
#pragma unroll
    for (int mi = 0; mi < 4; mi++)
#pragma unroll
        for (int nj = 0; nj < 4; nj++)
#pragma unroll
            for (int c = 0; c < 4; c++) acc[mi][nj][c] = 0.0f;

    gemm_core_tf32(x, B, HIDDEN, ldb, row0, col0, As, Bs, acc);

    int tid = threadIdx.x;
    int lane = tid & 31;
    int wi = tid >> 5;
    int g = lane >> 2;
    int t = lane & 3;
    int warp_m = (wi & 1) * 64;
    int warp_n = (wi >> 1) * 16;
    int wq = wi >> 1;

    if (donorm) {
        // row-wise sum of squares: shfl over t, then cross-warp via smem
        float ssl[4][2];
#pragma unroll
        for (int mi = 0; mi < 4; mi++)
#pragma unroll
            for (int hf = 0; hf < 2; hf++) {
                float s = 0.0f;
#pragma unroll
                for (int nj = 0; nj < 4; nj++)
#pragma unroll
                    for (int b2 = 0; b2 < 2; b2++) {
                        float v = acc[mi][nj][hf * 2 + b2];
                        s = fmaf(v, v, s);
                    }
                s += __shfl_xor_sync(0xffffffffu, s, 1);
                s += __shfl_xor_sync(0xffffffffu, s, 2);
                ssl[mi][hf] = s;
            }
        if (t == 0) {
#pragma unroll
            for (int mi = 0; mi < 4; mi++)
#pragma unroll
                for (int hf = 0; hf < 2; hf++)
                    sred[warp_m + mi * 16 + g + 8 * hf][wq] = ssl[mi][hf];
        }
        __syncthreads();

        // normalization weights (row-independent)
        float wv[4][2];
#pragma unroll
        for (int nj = 0; nj < 4; nj++) {
            int noff = (nj & 1) * 8 + (nj >> 1) * 64;
            wv[nj][0] = w[warp_n + noff + 2 * t];
            wv[nj][1] = w[warp_n + noff + 2 * t + 1];
        }

#pragma unroll
        for (int mi = 0; mi < 4; mi++)
#pragma unroll
            for (int hf = 0; hf < 2; hf++) {
                int row = warp_m + mi * 16 + g + 8 * hf;
                float tot = sred[row][0] + sred[row][1] + sred[row][2] + sred[row][3];
                float r = rsqrtf(tot * (1.0f / 128.0f) + 1e-6f);
                int token = row0 + row;
                int tp = token & (SEQ - 1);

                float nv[4][2];
#pragma unroll
                for (int nj = 0; nj < 4; nj++)
#pragma unroll
                    for (int b2 = 0; b2 < 2; b2++)
                        nv[nj][b2] = acc[mi][nj][hf * 2 + b2] * r * wv[nj][b2];

#pragma unroll
                for (int nj = 0; nj < 4; nj++) {
                    int noff = (nj & 1) * 8 + (nj >> 1) * 64;
                    int ci = warp_n + (nj & 1) * 8 + 2 * t;   // d & 63
                    float c0 = g_cosT[tp * 64 + ci];
                    float s0 = g_sinT[tp * 64 + ci];
                    float c1 = g_cosT[tp * 64 + ci + 1];
                    float s1 = g_sinT[tp * 64 + ci + 1];
                    float rot0 = (nj < 2) ? -nv[nj + 2][0] : nv[nj - 2][0];
                    float rot1 = (nj < 2) ? -nv[nj + 2][1] : nv[nj - 2][1];
                    float2 o2 = make_float2(nv[nj][0] * c0 + rot0 * s0,
                                            nv[nj][1] * c1 + rot1 * s1);
                    *(float2*)(C + (size_t)token * ldb + col0 + warp_n + noff + 2 * t) = o2;
                }
            }
    } else {
        // plain store (V)
#pragma unroll
        for (int mi = 0; mi < 4; mi++)
#pragma unroll
            for (int hf = 0; hf < 2; hf++) {
                int row = warp_m + mi * 16 + g + 8 * hf;
                int token = row0 + row;
#pragma unroll
                for (int nj = 0; nj < 4; nj++) {
                    int noff = (nj & 1) * 8 + (nj >> 1) * 64;
                    float2 o2 = make_float2(acc[mi][nj][hf * 2 + 0],
                                            acc[mi][nj][hf * 2 + 1]);
                    *(float2*)(C + (size_t)token * ldb + col0 + warp_n + noff + 2 * t) = o2;
                }
            }
    }
}

// ---------------------------------------------------------------------------
// Wo GEMM (tf32), plain epilogue. A = g_o [4096 x 2048], B = Wo [2048 x 1024]
// ---------------------------------------------------------------------------
__global__ __launch_bounds__(256, 2) void wo_tf32_kernel(
    const float* __restrict__ A, const float* __restrict__ B,
    float* __restrict__ C)
{
    __shared__ unsigned As[128 * AS_STR];
    __shared__ unsigned Bs[16 * BS_STR];

    int row0 = blockIdx.y * 128;
    int col0 = blockIdx.x * 128;

    float acc[4][4][4];
#pragma unroll
    for (int mi = 0; mi < 4; mi++)
#pragma unroll
        for (int nj = 0; nj < 4; nj++)
#pragma unroll
            for (int c = 0; c < 4; c++) acc[mi][nj][c] = 0.0f;

    gemm_core_tf32(A, B, Q_OUT, HIDDEN, row0, col0, As, Bs, acc);

    int tid = threadIdx.x;
    int lane = tid & 31;
    int wi = tid >> 5;
    int g = lane >> 2;
    int t = lane & 3;
    int warp_m = (wi & 1) * 64;
    int warp_n = (wi >> 1) * 16;

#pragma unroll
    for (int mi = 0; mi < 4; mi++)
#pragma unroll
        for (int hf = 0; hf < 2; hf++) {
            int row = row0 + warp_m + mi * 16 + g + 8 * hf;
#pragma unroll
            for (int nj = 0; nj < 4; nj++) {
                int noff = (nj & 1) * 8 + (nj >> 1) * 64;
                float2 o2 = make_float2(acc[mi][nj][hf * 2 + 0],
                                        acc[mi][nj][hf * 2 + 1]);
                *(float2*)(C + (size_t)row * HIDDEN + col0 + warp_n + noff + 2 * t) = o2;
            }
        }
}

// ---------------------------------------------------------------------------
// Flash attention, tf32 mma.sync, causal, GQA rep=2 (unchanged from R2)
// ---------------------------------------------------------------------------
#define KS_STR 132
#define VS_STR 136
#define PS_STR 68
#define FA2_SMEM ((64*KS_STR + 64*VS_STR + 128*PS_STR) * 4)

__global__ __launch_bounds__(256, 1) void flash_tf32_kernel(
    const float* __restrict__ Q, const float* __restrict__ K,
    const float* __restrict__ V, float* __restrict__ O)
{
    extern __shared__ unsigned smu[];
    unsigned* Ks = smu;                    // [64][132] tf32
    unsigned* Vs = Ks + 64 * KS_STR;       // [64][136] tf32
    unsigned* Ps = Vs + 64 * VS_STR;       // [128][68] tf32

    int qt = gridDim.x - 1 - blockIdx.x;   // big tiles first
    int h  = blockIdx.y;
    int b  = blockIdx.z;
    int kvh = h >> 1;
    int q0 = qt * 128;

    int tid = threadIdx.x;
    int w = tid >> 5;
    int lane = tid & 31;
    int g = lane >> 2;
    int t = lane & 3;

    int row0 = w * 16 + g;
    int row1 = row0 + 8;
    int qrow0 = q0 + row0;
    int qrow1 = q0 + row1;

    unsigned qf[16][4];
    {
        const float scale = 0.08838834764831845f;  // 1/sqrt(128)
        const float* qb0 = Q + ((size_t)(b * SEQ + qrow0) * NQ + h) * HDIM;
        const float* qb1 = Q + ((size_t)(b * SEQ + qrow1) * NQ + h) * HDIM;
#pragma unroll
        for (int ks = 0; ks < 16; ks++) {
            int c0 = ks * 8 + t;
            qf[ks][0] = cvt_tf32(qb0[c0] * scale);
            qf[ks][1] = cvt_tf32(qb1[c0] * scale);
            qf[ks][2] = cvt_tf32(qb0[c0 + 4] * scale);
            qf[ks][3] = cvt_tf32(qb1[c0 + 4] * scale);
        }
    }

    float of[16][4];
#pragma unroll
    for (int j = 0; j < 16; j++)
#pragma unroll
        for (int c = 0; c < 4; c++) of[j][c] = 0.0f;
    float m0 = -1e30f, m1 = -1e30f, l0 = 0.0f, l1 = 0.0f;

    int nkt = 2 * qt + 2;

    for (int kt = 0; kt < nkt; kt++) {
        int k0 = kt * 64;
        __syncthreads();
        {
            const float* kg = K + ((size_t)(b * SEQ + k0) * NKV + kvh) * HDIM;
            const float* vg = V + ((size_t)(b * SEQ + k0) * NKV + kvh) * HDIM;
#pragma unroll
            for (int it = 0; it < 8; it++) {
                int idx = tid + it * 256;
                int r = idx >> 5, c = (idx & 31) * 4;
                float4 k4 = *(const float4*)(kg + (size_t)r * KV_OUT + c);
                float4 v4 = *(const float4*)(vg + (size_t)r * KV_OUT + c);
                uint4 ku = make_uint4(cvt_tf32(k4.x), cvt_tf32(k4.y),
                                      cvt_tf32(k4.z), cvt_tf32(k4.w));
                uint4 vu = make_uint4(cvt_tf32(v4.x), cvt_tf32(v4.y),
                                      cvt_tf32(v4.z), cvt_tf32(v4.w));
                *(uint4*)(Ks + r * KS_STR + c) = ku;
                *(uint4*)(Vs + r * VS_STR + c) = vu;
            }
        }
        __syncthreads();

        if (k0 > q0 + w * 16 + 15) continue;

        float sf[8][4];
#pragma unroll
        for (int j = 0; j < 8; j++)
#pragma unroll
            for (int c = 0; c < 4; c++) sf[j][c] = 0.0f;

#pragma unroll
        for (int ks = 0; ks < 16; ks++) {
#pragma unroll
            for (int j = 0; j < 8; j++) {
                const unsigned* kr = Ks + (j * 8 + g) * KS_STR + ks * 8 + t;
                mma_tf32(sf[j], qf[ks], kr[0], kr[4]);
            }
        }

        if (kt >= nkt - 2) {
#pragma unroll
            for (int j = 0; j < 8; j++) {
                int kg0 = k0 + j * 8 + 2 * t;
                if (kg0 > qrow0)     sf[j][0] = -1e30f;
                if (kg0 + 1 > qrow0) sf[j][1] = -1e30f;
                if (kg0 > qrow1)     sf[j][2] = -1e30f;
                if (kg0 + 1 > qrow1) sf[j][3] = -1e30f;
            }
        }

        float mt0 = -1e30f, mt1 = -1e30f;
#pragma unroll
        for (int j = 0; j < 8; j++) {
            mt0 = fmaxf(mt0, fmaxf(sf[j][0], sf[j][1]));
            mt1 = fmaxf(mt1, fmaxf(sf[j][2], sf[j][3]));
        }
        mt0 = fmaxf(mt0, __shfl_xor_sync(0xffffffffu, mt0, 1));
        mt0 = fmaxf(mt0, __shfl_xor_sync(0xffffffffu, mt0, 2));
        mt1 = fmaxf(mt1, __shfl_xor_sync(0xffffffffu, mt1, 1));
        mt1 = fmaxf(mt1, __shfl_xor_sync(0xffffffffu, mt1, 2));

        float mn0 = fmaxf(m0, mt0), mn1 = fmaxf(m1, mt1);
        float corr0 = __expf(m0 - mn0), corr1 = __expf(m1 - mn1);
        m0 = mn0; m1 = mn1;

        float rs0 = 0.0f, rs1 = 0.0f;
#pragma unroll
        for (int j = 0; j < 8; j++) {
            sf[j][0] = __expf(sf[j][0] - mn0);
            sf[j][1] = __expf(sf[j][1] - mn0);
            sf[j][2] = __expf(sf[j][2] - mn1);
            sf[j][3] = __expf(sf[j][3] - mn1);
            rs0 += sf[j][0] + sf[j][1];
            rs1 += sf[j][2] + sf[j][3];
        }
        rs0 += __shfl_xor_sync(0xffffffffu, rs0, 1);
        rs0 += __shfl_xor_sync(0xffffffffu, rs0, 2);
        rs1 += __shfl_xor_sync(0xffffffffu, rs1, 1);
        rs1 += __shfl_xor_sync(0xffffffffu, rs1, 2);
        l0 = l0 * corr0 + rs0;
        l1 = l1 * corr1 + rs1;

#pragma unroll
        for (int j = 0; j < 16; j++) {
            of[j][0] *= corr0; of[j][1] *= corr0;
            of[j][2] *= corr1; of[j][3] *= corr1;
        }

#pragma unroll
        for (int j = 0; j < 8; j++) {
            uint2 p01 = make_uint2(cvt_tf32(sf[j][0]), cvt_tf32(sf[j][1]));
            uint2 p23 = make_uint2(cvt_tf32(sf[j][2]), cvt_tf32(sf[j][3]));
            *(uint2*)(Ps + row0 * PS_STR + j * 8 + 2 * t) = p01;
            *(uint2*)(Ps + row1 * PS_STR + j * 8 + 2 * t) = p23;
        }
        __syncwarp();

#pragma unroll
        for (int ks = 0; ks < 8; ks++) {
            unsigned pa[4];
            pa[0] = Ps[row0 * PS_STR + ks * 8 + t];
            pa[1] = Ps[row1 * PS_STR + ks * 8 + t];
            pa[2] = Ps[row0 * PS_STR + ks * 8 + t + 4];
            pa[3] = Ps[row1 * PS_STR + ks * 8 + t + 4];
#pragma unroll
            for (int j = 0; j < 16; j++) {
                unsigned b0 = Vs[(ks * 8 + t) * VS_STR + j * 8 + g];
                unsigned b1 = Vs[(ks * 8 + t + 4) * VS_STR + j * 8 + g];
                mma_tf32(of[j], pa, b0, b1);
            }
        }
    }

    float inv0 = 1.0f / l0, inv1 = 1.0f / l1;
    float* og0 = O + ((size_t)(b * SEQ + qrow0) * NQ + h) * HDIM;
    float* og1 = O + ((size_t)(b * SEQ + qrow1) * NQ + h) * HDIM;
#pragma unroll
    for (int j = 0; j < 16; j++) {
        float2 v0 = make_float2(of[j][0] * inv0, of[j][1] * inv0);
        float2 v1 = make_float2(of[j][2] * inv1, of[j][3] * inv1);
        *(float2*)(og0 + j * 8 + 2 * t) = v0;
        *(float2*)(og1 + j * 8 + 2 * t) = v1;
    }
}

// ---------------------------------------------------------------------------
// Launch
// ---------------------------------------------------------------------------
extern "C" void kernel_launch(void* const* d_in, const int* in_sizes, int n_in,
                              void* d_out, int out_size)
{
    const float* x  = (const float*)d_in[0];
    const float* Wq = (const float*)d_in[1];
    const float* Wk = (const float*)d_in[2];
    const float* Wv = (const float*)d_in[3];
    const float* Wo = (const float*)d_in[4];
    const float* qw = (const float*)d_in[5];
    const float* kw = (const float*)d_in[6];
    float* out = (float*)d_out;

    float *pq, *pk, *pv, *po;
    cudaGetSymbolAddress((void**)&pq, g_q);
    cudaGetSymbolAddress((void**)&pk, g_k);
    cudaGetSymbolAddress((void**)&pv, g_v);
    cudaGetSymbolAddress((void**)&po, g_o);

    // RoPE tables
    rope_table_kernel<<<SEQ, 64>>>();

    // Fused QKV projection (tf32 tensor cores) + RMSNorm + RoPE epilogue
    qkv_tf32_kernel<<<dim3(32, TOKENS / 128), 256>>>(x, Wq, Wk, Wv, qw, kw);

    // Flash attention (tf32 tensor cores)
    cudaFuncSetAttribute(flash_tf32_kernel,
                         cudaFuncAttributeMaxDynamicSharedMemorySize, FA2_SMEM);
    flash_tf32_kernel<<<dim3(SEQ / 128, NQ, BATCH), 256, FA2_SMEM>>>(pq, pk, pv, po);

    // Output projection (tf32 tensor cores)
    wo_tf32_kernel<<<dim3(HIDDEN / 128, TOKENS / 128), 256>>>(po, Wo, out);
}

// round 4
// speedup vs baseline: 4.4508x; 1.0195x over previous
#include <cuda_runtime.h>
#include <cuda_bf16.h>
#include <math.h>

// ---------------------------------------------------------------------------
// Problem constants
// ---------------------------------------------------------------------------
#define BATCH   2
#define SEQ     2048
#define HIDDEN  1024
#define Q_OUT   2048
#define KV_OUT  1024
#define HDIM    128
#define NQ      16
#define NKV     8
#define TOKENS  (BATCH*SEQ)          // 4096

// ---------------------------------------------------------------------------
// Scratch (device globals; no allocation allowed)
// ---------------------------------------------------------------------------
__device__ float g_q[TOKENS * Q_OUT];
__device__ float g_k[TOKENS * KV_OUT];
__device__ float g_v[TOKENS * KV_OUT];
__device__ float g_o[TOKENS * Q_OUT];
__device__ float g_cosT[SEQ * 64];
__device__ float g_sinT[SEQ * 64];

// ---------------------------------------------------------------------------
// tf32 / cp.async helpers
// ---------------------------------------------------------------------------
__device__ __forceinline__ unsigned cvt_tf32(float f) {
    unsigned u;
    asm("cvt.rna.tf32.f32 %0, %1;" : "=r"(u) : "f"(f));
    return u;
}

__device__ __forceinline__ void mma_tf32(float* c, const unsigned* a,
                                         unsigned b0, unsigned b1) {
    asm("mma.sync.aligned.m16n8k8.row.col.f32.tf32.tf32.f32 "
        "{%0,%1,%2,%3}, {%4,%5,%6,%7}, {%8,%9}, {%0,%1,%2,%3};"
        : "+f"(c[0]), "+f"(c[1]), "+f"(c[2]), "+f"(c[3])
        : "r"(a[0]), "r"(a[1]), "r"(a[2]), "r"(a[3]), "r"(b0), "r"(b1));
}

__device__ __forceinline__ void cp_async16(unsigned dst_smem, const void* src) {
    asm volatile("cp.async.cg.shared.global [%0], [%1], 16;\n"
                 :: "r"(dst_smem), "l"(src));
}
#define CP_COMMIT()  asm volatile("cp.async.commit_group;\n" ::: "memory")
#define CP_WAIT(N)   asm volatile("cp.async.wait_group %0;\n" :: "n"(N) : "memory")

// ---------------------------------------------------------------------------
// RoPE cos/sin table
// ---------------------------------------------------------------------------
__global__ void rope_table_kernel() {
    int t = blockIdx.x;
    int j = threadIdx.x;   // 0..63
    float e = (float)j * (1.0f / 64.0f);
    float inv = exp2f(-e * 13.287712379549449f);  // log2(10000)
    float a = (float)t * inv;
    float s, c;
    sincosf(a, &s, &c);
    g_cosT[t * 64 + j] = c;
    g_sinT[t * 64 + j] = s;
}

// ---------------------------------------------------------------------------
// tf32 GEMM core with depth-3 cp.async staging pipeline.
// 128x128 block tile, BK=16, 256 threads (8 warps, 2m x 4n).
// Dynamic smem layout (unsigned units):
//   SgA: 3 * 2048 fp32   (staging A tiles, raw fp32)
//   SgB: 3 * 2048 fp32
//   As : 128*20 tf32     (mma layout, [m][k])
//   Bs : 16*136 tf32     ([k][n])
//   sred: 128*4 fp32     (qkv only)
// ---------------------------------------------------------------------------
#define AS_STR 20
#define BS_STR 136
#define SGA_ELEMS 2048
#define SGB_ELEMS 2048
#define GEMM_SMEM ((3*SGA_ELEMS + 3*SGB_ELEMS + 128*AS_STR + 16*BS_STR + 512) * 4)

__device__ __forceinline__ void gemm_core_tf32(
    const float* __restrict__ A, const float* __restrict__ B,
    int K, int ldb, int row0, int col0,
    float* SgA, float* SgB, unsigned* As, unsigned* Bs, float acc[4][4][4])
{
    int tid = threadIdx.x;
    int lane = tid & 31;
    int wi = tid >> 5;
    int g = lane >> 2;
    int t = lane & 3;
    int warp_m = (wi & 1) * 64;
    int warp_n = (wi >> 1) * 16;

    unsigned sga_u = (unsigned)__cvta_generic_to_shared(SgA);
    unsigned sgb_u = (unsigned)__cvta_generic_to_shared(SgB);

    // per-thread copy indices
    int am = tid >> 2, akq = (tid & 3) * 4;           // +128 rows on it=1
    int bkb = tid >> 5, bnq = (tid & 31) * 4;         // +8 k-rows on it=1

    const int nsteps = K >> 4;

    // issue stage s into staging buffer buf
#define GEMM_ISSUE(s, buf) do {                                               \
        int k0_ = (s) * 16;                                                   \
        unsigned a_base = sga_u + (buf) * (SGA_ELEMS * 4);                    \
        unsigned b_base = sgb_u + (buf) * (SGB_ELEMS * 4);                    \
        cp_async16(a_base + (am * 16 + akq) * 4,                              \
                   A + (size_t)(row0 + am) * K + k0_ + akq);                  \
        cp_async16(a_base + ((am + 64) * 16 + akq) * 4,                       \
                   A + (size_t)(row0 + am + 64) * K + k0_ + akq);             \
        cp_async16(b_base + (bkb * 128 + bnq) * 4,                            \
                   B + (size_t)(k0_ + bkb) * ldb + col0 + bnq);               \
        cp_async16(b_base + ((bkb + 8) * 128 + bnq) * 4,                      \
                   B + (size_t)(k0_ + bkb + 8) * ldb + col0 + bnq);           \
        CP_COMMIT();                                                          \
    } while (0)

    GEMM_ISSUE(0, 0);
    GEMM_ISSUE(1, 1);

    int buf = 0;
    for (int s = 0; s < nsteps; s++) {
        CP_WAIT(1);
        __syncthreads();

        // convert staging fp32 -> tf32 mma buffers
        {
            float* sa = SgA + buf * SGA_ELEMS;
            float* sb = SgB + buf * SGB_ELEMS;
            float4 a0 = *(float4*)(sa + am * 16 + akq);
            float4 a1 = *(float4*)(sa + (am + 64) * 16 + akq);
            float4 b0 = *(float4*)(sb + bkb * 128 + bnq);
            float4 b1 = *(float4*)(sb + (bkb + 8) * 128 + bnq);
            *(uint4*)(As + am * AS_STR + akq) =
                make_uint4(cvt_tf32(a0.x), cvt_tf32(a0.y), cvt_tf32(a0.z), cvt_tf32(a0.w));
            *(uint4*)(As + (am + 64) * AS_STR + akq) =
                make_uint4(cvt_tf32(a1.x), cvt_tf32(a1.y), cvt_tf32(a1.z), cvt_tf32(a1.w));
            *(uint4*)(Bs + bkb * BS_STR + bnq) =
                make_uint4(cvt_tf32(b0.x), cvt_tf32(b0.y), cvt_tf32(b0.z), cvt_tf32(b0.w));
            *(uint4*)(Bs + (bkb + 8) * BS_STR + bnq) =
                make_uint4(cvt_tf32(b1.x), cvt_tf32(b1.y), cvt_tf32(b1.z), cvt_tf32(b1.w));
        }
        __syncthreads();

        // keep exactly one commit per iteration for wait_group accounting
        if (s + 2 < nsteps) {
            int nb = buf + 2; if (nb >= 3) nb -= 3;
            GEMM_ISSUE(s + 2, nb);
        } else {
            CP_COMMIT();
        }

        // compute from As/Bs
#pragma unroll
        for (int ks = 0; ks < 2; ks++) {
            unsigned af[4][4], bf[4][2];
#pragma unroll
            for (int mi = 0; mi < 4; mi++) {
                int mb = warp_m + mi * 16;
                af[mi][0] = As[(mb + g) * AS_STR + ks * 8 + t];
                af[mi][1] = As[(mb + g + 8) * AS_STR + ks * 8 + t];
                af[mi][2] = As[(mb + g) * AS_STR + ks * 8 + t + 4];
                af[mi][3] = As[(mb + g + 8) * AS_STR + ks * 8 + t + 4];
            }
#pragma unroll
            for (int nj = 0; nj < 4; nj++) {
                int noff = (nj & 1) * 8 + (nj >> 1) * 64;   // {0,8,64,72}
                int cb = warp_n + noff + g;
                bf[nj][0] = Bs[(ks * 8 + t) * BS_STR + cb];
                bf[nj][1] = Bs[(ks * 8 + t + 4) * BS_STR + cb];
            }
#pragma unroll
            for (int mi = 0; mi < 4; mi++)
#pragma unroll
                for (int nj = 0; nj < 4; nj++)
                    mma_tf32(acc[mi][nj], af[mi], bf[nj][0], bf[nj][1]);
        }

        buf++; if (buf == 3) buf = 0;
    }
#undef GEMM_ISSUE
}

// ---------------------------------------------------------------------------
// Fused QKV GEMM (tf32) + per-head RMSNorm + RoPE epilogue for Q/K
// ---------------------------------------------------------------------------
__global__ __launch_bounds__(256, 2) void qkv_tf32_kernel(
    const float* __restrict__ x,
    const float* __restrict__ Wq, const float* __restrict__ Wk,
    const float* __restrict__ Wv,
    const float* __restrict__ qw, const float* __restrict__ kw)
{
    extern __shared__ unsigned dsm[];
    float* SgA = (float*)dsm;
    float* SgB = SgA + 3 * SGA_ELEMS;
    unsigned* As = (unsigned*)(SgB + 3 * SGB_ELEMS);
    unsigned* Bs = As + 128 * AS_STR;
    float (*sred)[4] = (float(*)[4])(Bs + 16 * BS_STR);

    int bx = blockIdx.x;
    const float* B; float* C; const float* w; int ldb, col0, donorm;
    if (bx < 16)      { B = Wq; C = g_q; ldb = Q_OUT;  col0 = bx * 128;        donorm = 1; w = qw; }
    else if (bx < 24) { B = Wk; C = g_k; ldb = KV_OUT; col0 = (bx - 16) * 128; donorm = 1; w = kw; }
    else              { B = Wv; C = g_v; ldb = KV_OUT; col0 = (bx - 24) * 128; donorm = 0; w = qw; }

    int row0 = blockIdx.y * 128;

    float acc[4][4][4];
#pragma unroll
    for (int mi = 0; mi < 4; mi++)
#pragma unroll
        for (int nj = 0; nj < 4; nj++)
#pragma unroll
            for (int c = 0; c < 4; c++) acc[mi][nj][c] = 0.0f;

    gemm_core_tf32(x, B, HIDDEN, ldb, row0, col0, SgA, SgB, As, Bs, acc);

    int tid = threadIdx.x;
    int lane = tid & 31;
    int wi = tid >> 5;
    int g = lane >> 2;
    int t = lane & 3;
    int warp_m = (wi & 1) * 64;
    int warp_n = (wi >> 1) * 16;
    int wq = wi >> 1;

    if (donorm) {
        float ssl[4][2];
#pragma unroll
        for (int mi = 0; mi < 4; mi++)
#pragma unroll
            for (int hf = 0; hf < 2; hf++) {
                float s = 0.0f;
#pragma unroll
                for (int nj = 0; nj < 4; nj++)
#pragma unroll
                    for (int b2 = 0; b2 < 2; b2++) {
                        float v = acc[mi][nj][hf * 2 + b2];
                        s = fmaf(v, v, s);
                    }
                s += __shfl_xor_sync(0xffffffffu, s, 1);
                s += __shfl_xor_sync(0xffffffffu, s, 2);
                ssl[mi][hf] = s;
            }
        __syncthreads();   // protect sred vs As/Bs region reuse (different mem, but cheap safety vs gemm tail)
        if (t == 0) {
#pragma unroll
            for (int mi = 0; mi < 4; mi++)
#pragma unroll
                for (int hf = 0; hf < 2; hf++)
                    sred[warp_m + mi * 16 + g + 8 * hf][wq] = ssl[mi][hf];
        }
        __syncthreads();

        float wv[4][2];
#pragma unroll
        for (int nj = 0; nj < 4; nj++) {
            int noff = (nj & 1) * 8 + (nj >> 1) * 64;
            wv[nj][0] = w[warp_n + noff + 2 * t];
            wv[nj][1] = w[warp_n + noff + 2 * t + 1];
        }

#pragma unroll
        for (int mi = 0; mi < 4; mi++)
#pragma unroll
            for (int hf = 0; hf < 2; hf++) {
                int row = warp_m + mi * 16 + g + 8 * hf;
                float tot = sred[row][0] + sred[row][1] + sred[row][2] + sred[row][3];
                float r = rsqrtf(tot * (1.0f / 128.0f) + 1e-6f);
                int token = row0 + row;
                int tp = token & (SEQ - 1);

                float nv[4][2];
#pragma unroll
                for (int nj = 0; nj < 4; nj++)
#pragma unroll
                    for (int b2 = 0; b2 < 2; b2++)
                        nv[nj][b2] = acc[mi][nj][hf * 2 + b2] * r * wv[nj][b2];

#pragma unroll
                for (int nj = 0; nj < 4; nj++) {
                    int noff = (nj & 1) * 8 + (nj >> 1) * 64;
                    int ci = warp_n + (nj & 1) * 8 + 2 * t;   // d & 63
                    float c0 = g_cosT[tp * 64 + ci];
                    float s0 = g_sinT[tp * 64 + ci];
                    float c1 = g_cosT[tp * 64 + ci + 1];
                    float s1 = g_sinT[tp * 64 + ci + 1];
                    float rot0 = (nj < 2) ? -nv[nj + 2][0] : nv[nj - 2][0];
                    float rot1 = (nj < 2) ? -nv[nj + 2][1] : nv[nj - 2][1];
                    float2 o2 = make_float2(nv[nj][0] * c0 + rot0 * s0,
                                            nv[nj][1] * c1 + rot1 * s1);
                    *(float2*)(C + (size_t)token * ldb + col0 + warp_n + noff + 2 * t) = o2;
                }
            }
    } else {
#pragma unroll
        for (int mi = 0; mi < 4; mi++)
#pragma unroll
            for (int hf = 0; hf < 2; hf++) {
                int row = warp_m + mi * 16 + g + 8 * hf;
                int token = row0 + row;
#pragma unroll
                for (int nj = 0; nj < 4; nj++) {
                    int noff = (nj & 1) * 8 + (nj >> 1) * 64;
                    float2 o2 = make_float2(acc[mi][nj][hf * 2 + 0],
                                            acc[mi][nj][hf * 2 + 1]);
                    *(float2*)(C + (size_t)token * ldb + col0 + warp_n + noff + 2 * t) = o2;
                }
            }
    }
}

// ---------------------------------------------------------------------------
// Wo GEMM (tf32)
// ---------------------------------------------------------------------------
__global__ __launch_bounds__(256, 2) void wo_tf32_kernel(
    const float* __restrict__ A, const float* __restrict__ B,
    float* __restrict__ C)
{
    extern __shared__ unsigned dsm[];
    float* SgA = (float*)dsm;
    float* SgB = SgA + 3 * SGA_ELEMS;
    unsigned* As = (unsigned*)(SgB + 3 * SGB_ELEMS);
    unsigned* Bs = As + 128 * AS_STR;

    int row0 = blockIdx.y * 128;
    int col0 = blockIdx.x * 128;

    float acc[4][4][4];
#pragma unroll
    for (int mi = 0; mi < 4; mi++)
#pragma unroll
        for (int nj = 0; nj < 4; nj++)
#pragma unroll
            for (int c = 0; c < 4; c++) acc[mi][nj][c] = 0.0f;

    gemm_core_tf32(A, B, Q_OUT, HIDDEN, row0, col0, SgA, SgB, As, Bs, acc);

    int tid = threadIdx.x;
    int lane = tid & 31;
    int wi = tid >> 5;
    int g = lane >> 2;
    int t = lane & 3;
    int warp_m = (wi & 1) * 64;
    int warp_n = (wi >> 1) * 16;

#pragma unroll
    for (int mi = 0; mi < 4; mi++)
#pragma unroll
        for (int hf = 0; hf < 2; hf++) {
            int row = row0 + warp_m + mi * 16 + g + 8 * hf;
#pragma unroll
            for (int nj = 0; nj < 4; nj++) {
                int noff = (nj & 1) * 8 + (nj >> 1) * 64;
                float2 o2 = make_float2(acc[mi][nj][hf * 2 + 0],
                                        acc[mi][nj][hf * 2 + 1]);
                *(float2*)(C + (size_t)row * HIDDEN + col0 + warp_n + noff + 2 * t) = o2;
            }
        }
}

// ---------------------------------------------------------------------------
// Flash attention, tf32 mma.sync, causal, GQA rep=2, cp.async K/V staging
// ---------------------------------------------------------------------------
#define KS_STR 132
#define VS_STR 136
#define PS_STR 68
#define FA2_SMEM ((64*KS_STR + 64*VS_STR + 128*PS_STR + 2*64*128) * 4)

__global__ __launch_bounds__(256, 1) void flash_tf32_kernel(
    const float* __restrict__ Q, const float* __restrict__ K,
    const float* __restrict__ V, float* __restrict__ O)
{
    extern __shared__ unsigned smu[];
    unsigned* Ks = smu;                        // [64][132] tf32
    unsigned* Vs = Ks + 64 * KS_STR;           // [64][136] tf32
    unsigned* Ps = Vs + 64 * VS_STR;           // [128][68] tf32
    float* SgK = (float*)(Ps + 128 * PS_STR);  // [64][128] fp32 staging
    float* SgV = SgK + 64 * 128;               // [64][128]

    unsigned sgk_u = (unsigned)__cvta_generic_to_shared(SgK);
    unsigned sgv_u = (unsigned)__cvta_generic_to_shared(SgV);

    int qt = gridDim.x - 1 - blockIdx.x;   // big tiles first
    int h  = blockIdx.y;
    int b  = blockIdx.z;
    int kvh = h >> 1;
    int q0 = qt * 128;

    int tid = threadIdx.x;
    int w = tid >> 5;
    int lane = tid & 31;
    int g = lane >> 2;
    int t = lane & 3;

    int row0 = w * 16 + g;
    int row1 = row0 + 8;
    int qrow0 = q0 + row0;
    int qrow1 = q0 + row1;

    const float* Kbase = K + ((size_t)b * SEQ * NKV + kvh) * HDIM;
    const float* Vbase = V + ((size_t)b * SEQ * NKV + kvh) * HDIM;

    int nkt = 2 * qt + 2;

    // issue cp.async for tile kt
#define FA_ISSUE(kt_) do {                                                    \
        const float* kg_ = Kbase + (size_t)(kt_) * 64 * KV_OUT;               \
        const float* vg_ = Vbase + (size_t)(kt_) * 64 * KV_OUT;               \
        _Pragma("unroll")                                                     \
        for (int it = 0; it < 8; it++) {                                      \
            int idx = tid + it * 256;                                         \
            int r_ = idx >> 5, c_ = (idx & 31) * 4;                           \
            cp_async16(sgk_u + (r_ * 128 + c_) * 4, kg_ + (size_t)r_ * KV_OUT + c_); \
            cp_async16(sgv_u + (r_ * 128 + c_) * 4, vg_ + (size_t)r_ * KV_OUT + c_); \
        }                                                                     \
        CP_COMMIT();                                                          \
    } while (0)

    FA_ISSUE(0);

    // Q fragments in registers (pre-scaled, tf32) — overlaps with cp.async
    unsigned qf[16][4];
    {
        const float scale = 0.08838834764831845f;  // 1/sqrt(128)
        const float* qb0 = Q + ((size_t)(b * SEQ + qrow0) * NQ + h) * HDIM;
        const float* qb1 = Q + ((size_t)(b * SEQ + qrow1) * NQ + h) * HDIM;
#pragma unroll
        for (int ks = 0; ks < 16; ks++) {
            int c0 = ks * 8 + t;
            qf[ks][0] = cvt_tf32(qb0[c0] * scale);
            qf[ks][1] = cvt_tf32(qb1[c0] * scale);
            qf[ks][2] = cvt_tf32(qb0[c0 + 4] * scale);
            qf[ks][3] = cvt_tf32(qb1[c0 + 4] * scale);
        }
    }

    float of[16][4];
#pragma unroll
    for (int j = 0; j < 16; j++)
#pragma unroll
        for (int c = 0; c < 4; c++) of[j][c] = 0.0f;
    float m0 = -1e30f, m1 = -1e30f, l0 = 0.0f, l1 = 0.0f;

    for (int kt = 0; kt < nkt; kt++) {
        int k0 = kt * 64;

        CP_WAIT(0);
        __syncthreads();

        // convert staging fp32 -> tf32 mma buffers
#pragma unroll
        for (int it = 0; it < 8; it++) {
            int idx = tid + it * 256;
            int r = idx >> 5, c = (idx & 31) * 4;
            float4 k4 = *(float4*)(SgK + r * 128 + c);
            float4 v4 = *(float4*)(SgV + r * 128 + c);
            *(uint4*)(Ks + r * KS_STR + c) =
                make_uint4(cvt_tf32(k4.x), cvt_tf32(k4.y), cvt_tf32(k4.z), cvt_tf32(k4.w));
            *(uint4*)(Vs + r * VS_STR + c) =
                make_uint4(cvt_tf32(v4.x), cvt_tf32(v4.y), cvt_tf32(v4.z), cvt_tf32(v4.w));
        }
        __syncthreads();

        // prefetch next tile behind compute
        if (kt + 1 < nkt) FA_ISSUE(kt + 1);

        // fully-masked warps skip compute (syncs already done)
        if (k0 > q0 + w * 16 + 15) continue;

        // --- S = Q @ K^T ---
        float sf[8][4];
#pragma unroll
        for (int j = 0; j < 8; j++)
#pragma unroll
            for (int c = 0; c < 4; c++) sf[j][c] = 0.0f;

#pragma unroll
        for (int ks = 0; ks < 16; ks++) {
#pragma unroll
            for (int j = 0; j < 8; j++) {
                const unsigned* kr = Ks + (j * 8 + g) * KS_STR + ks * 8 + t;
                mma_tf32(sf[j], qf[ks], kr[0], kr[4]);
            }
        }

        if (kt >= nkt - 2) {
#pragma unroll
            for (int j = 0; j < 8; j++) {
                int kg0 = k0 + j * 8 + 2 * t;
                if (kg0 > qrow0)     sf[j][0] = -1e30f;
                if (kg0 + 1 > qrow0) sf[j][1] = -1e30f;
                if (kg0 > qrow1)     sf[j][2] = -1e30f;
                if (kg0 + 1 > qrow1) sf[j][3] = -1e30f;
            }
        }

        // --- online softmax ---
        float mt0 = -1e30f, mt1 = -1e30f;
#pragma unroll
        for (int j = 0; j < 8; j++) {
            mt0 = fmaxf(mt0, fmaxf(sf[j][0], sf[j][1]));
            mt1 = fmaxf(mt1, fmaxf(sf[j][2], sf[j][3]));
        }
        mt0 = fmaxf(mt0, __shfl_xor_sync(0xffffffffu, mt0, 1));
        mt0 = fmaxf(mt0, __shfl_xor_sync(0xffffffffu, mt0, 2));
        mt1 = fmaxf(mt1, __shfl_xor_sync(0xffffffffu, mt1, 1));
        mt1 = fmaxf(mt1, __shfl_xor_sync(0xffffffffu, mt1, 2));

        float mn0 = fmaxf(m0, mt0), mn1 = fmaxf(m1, mt1);
        float corr0 = __expf(m0 - mn0), corr1 = __expf(m1 - mn1);
        m0 = mn0; m1 = mn1;

        float rs0 = 0.0f, rs1 = 0.0f;
#pragma unroll
        for (int j = 0; j < 8; j++) {
            sf[j][0] = __expf(sf[j][0] - mn0);
            sf[j][1] = __expf(sf[j][1] - mn0);
            sf[j][2] = __expf(sf[j][2] - mn1);
            sf[j][3] = __expf(sf[j][3] - mn1);
            rs0 += sf[j][0] + sf[j][1];
            rs1 += sf[j][2] + sf[j][3];
        }
        rs0 += __shfl_xor_sync(0xffffffffu, rs0, 1);
        rs0 += __shfl_xor_sync(0xffffffffu, rs0, 2);
        rs1 += __shfl_xor_sync(0xffffffffu, rs1, 1);
        rs1 += __shfl_xor_sync(0xffffffffu, rs1, 2);
        l0 = l0 * corr0 + rs0;
        l1 = l1 * corr1 + rs1;

#pragma unroll
        for (int j = 0; j < 16; j++) {
            of[j][0] *= corr0; of[j][1] *= corr0;
            of[j][2] *= corr1; of[j][3] *= corr1;
        }

        // --- P via smem relayout (warp-private rows) ---
#pragma unroll
        for (int j = 0; j < 8; j++) {
            uint2 p01 = make_uint2(cvt_tf32(sf[j][0]), cvt_tf32(sf[j][1]));
            uint2 p23 = make_uint2(cvt_tf32(sf[j][2]), cvt_tf32(sf[j][3]));
            *(uint2*)(Ps + row0 * PS_STR + j * 8 + 2 * t) = p01;
            *(uint2*)(Ps + row1 * PS_STR + j * 8 + 2 * t) = p23;
        }
        __syncwarp();

        // --- O += P @ V ---
#pragma unroll
        for (int ks = 0; ks < 8; ks++) {
            unsigned pa[4];
            pa[0] = Ps[row0 * PS_STR + ks * 8 + t];
            pa[1] = Ps[row1 * PS_STR + ks * 8 + t];
            pa[2] = Ps[row0 * PS_STR + ks * 8 + t + 4];
            pa[3] = Ps[row1 * PS_STR + ks * 8 + t + 4];
#pragma unroll
            for (int j = 0; j < 16; j++) {
                unsigned b0 = Vs[(ks * 8 + t) * VS_STR + j * 8 + g];
                unsigned b1 = Vs[(ks * 8 + t + 4) * VS_STR + j * 8 + g];
                mma_tf32(of[j], pa, b0, b1);
            }
        }
    }
#undef FA_ISSUE

    float inv0 = 1.0f / l0, inv1 = 1.0f / l1;
    float* og0 = O + ((size_t)(b * SEQ + qrow0) * NQ + h) * HDIM;
    float* og1 = O + ((size_t)(b * SEQ + qrow1) * NQ + h) * HDIM;
#pragma unroll
    for (int j = 0; j < 16; j++) {
        float2 v0 = make_float2(of[j][0] * inv0, of[j][1] * inv0);
        float2 v1 = make_float2(of[j][2] * inv1, of[j][3] * inv1);
        *(float2*)(og0 + j * 8 + 2 * t) = v0;
        *(float2*)(og1 + j * 8 + 2 * t) = v1;
    }
}

// ---------------------------------------------------------------------------
// Launch
// ---------------------------------------------------------------------------
extern "C" void kernel_launch(void* const* d_in, const int* in_sizes, int n_in,
                              void* d_out, int out_size)
{
    const float* x  = (const float*)d_in[0];
    const float* Wq = (const float*)d_in[1];
    const float* Wk = (const float*)d_in[2];
    const float* Wv = (const float*)d_in[3];
    const float* Wo = (const float*)d_in[4];
    const float* qw = (const float*)d_in[5];
    const float* kw = (const float*)d_in[6];
    float* out = (float*)d_out;

    float *pq, *pk, *pv, *po;
    cudaGetSymbolAddress((void**)&pq, g_q);
    cudaGetSymbolAddress((void**)&pk, g_k);
    cudaGetSymbolAddress((void**)&pv, g_v);
    cudaGetSymbolAddress((void**)&po, g_o);

    cudaFuncSetAttribute(qkv_tf32_kernel,
                         cudaFuncAttributeMaxDynamicSharedMemorySize, GEMM_SMEM);
    cudaFuncSetAttribute(wo_tf32_kernel,
                         cudaFuncAttributeMaxDynamicSharedMemorySize, GEMM_SMEM);
    cudaFuncSetAttribute(flash_tf32_kernel,
                         cudaFuncAttributeMaxDynamicSharedMemorySize, FA2_SMEM);

    // RoPE tables
    rope_table_kernel<<<SEQ, 64>>>();

    // Fused QKV projection (tf32) + RMSNorm + RoPE epilogue
    qkv_tf32_kernel<<<dim3(32, TOKENS / 128), 256, GEMM_SMEM>>>(x, Wq, Wk, Wv, qw, kw);

    // Flash attention (tf32, cp.async pipelined)
    flash_tf32_kernel<<<dim3(SEQ / 128, NQ, BATCH), 256, FA2_SMEM>>>(pq, pk, pv, po);

    // Output projection (tf32)
    wo_tf32_kernel<<<dim3(HIDDEN / 128, TOKENS / 128), 256, GEMM_SMEM>>>(po, Wo, out);
}

// round 5
// speedup vs baseline: 6.2633x; 1.4072x over previous
#include <cuda_runtime.h>
#include <cuda_fp16.h>
#include <math.h>

// ---------------------------------------------------------------------------
// Problem constants
// ---------------------------------------------------------------------------
#define BATCH   2
#define SEQ     2048
#define HIDDEN  1024
#define Q_OUT   2048
#define KV_OUT  1024
#define HDIM    128
#define NQ      16
#define NKV     8
#define TOKENS  (BATCH*SEQ)          // 4096

// ---------------------------------------------------------------------------
// Scratch (device globals; no allocation allowed)
// ---------------------------------------------------------------------------
__device__ float g_q[TOKENS * Q_OUT];
__device__ float g_k[TOKENS * KV_OUT];
__device__ float g_v[TOKENS * KV_OUT];
__device__ float g_o[TOKENS * Q_OUT];
__device__ float g_cosT[SEQ * 64];
__device__ float g_sinT[SEQ * 64];

// ---------------------------------------------------------------------------
// helpers
// ---------------------------------------------------------------------------
__device__ __forceinline__ unsigned pack_h2(float lo, float hi) {
    unsigned u;
    asm("cvt.rn.f16x2.f32 %0, %2, %1;" : "=r"(u) : "f"(lo), "f"(hi));
    return u;
}

__device__ __forceinline__ void mma_f16(float* c, const unsigned* a,
                                        unsigned b0, unsigned b1) {
    asm("mma.sync.aligned.m16n8k16.row.col.f32.f16.f16.f32 "
        "{%0,%1,%2,%3}, {%4,%5,%6,%7}, {%8,%9}, {%0,%1,%2,%3};"
        : "+f"(c[0]), "+f"(c[1]), "+f"(c[2]), "+f"(c[3])
        : "r"(a[0]), "r"(a[1]), "r"(a[2]), "r"(a[3]), "r"(b0), "r"(b1));
}

__device__ __forceinline__ void cp_async16(unsigned dst_smem, const void* src) {
    asm volatile("cp.async.cg.shared.global [%0], [%1], 16;\n"
                 :: "r"(dst_smem), "l"(src));
}
#define CP_COMMIT()  asm volatile("cp.async.commit_group;\n" ::: "memory")
#define CP_WAIT(N)   asm volatile("cp.async.wait_group %0;\n" :: "n"(N) : "memory")

// ---------------------------------------------------------------------------
// RoPE cos/sin table
// ---------------------------------------------------------------------------
__global__ void rope_table_kernel() {
    int t = blockIdx.x;
    int j = threadIdx.x;   // 0..63
    float e = (float)j * (1.0f / 64.0f);
    float inv = exp2f(-e * 13.287712379549449f);  // log2(10000)
    float a = (float)t * inv;
    float s, c;
    sincosf(a, &s, &c);
    g_cosT[t * 64 + j] = c;
    g_sinT[t * 64 + j] = s;
}

// ---------------------------------------------------------------------------
// fp16 GEMM core: 128x128 block tile, BK=32, 256 threads (8 warps, 2m x 4n).
// Depth-2 cp.async raw-fp32 staging; converted to half2 mma buffers:
//   As2[m][kk]: half2 pairs along k, stride 20 (frags at (20g+t)%32 distinct)
//   Bs2[kk][n]: half2 pairs along k, stride 136 ((8t+g)%32 distinct)
// Warp tile 64x32, n-offsets {0,8,64,72} (closed under +-64 for RoPE epilogue)
// ---------------------------------------------------------------------------
#define AS2_STR 20
#define BS2_STR 136
#define SGA_ELEMS 4096          // 128x32 fp32
#define SGB_ELEMS 4096          // 32x128 fp32
#define GEMM_SMEM ((2*SGA_ELEMS + 2*SGB_ELEMS + 128*AS2_STR + 16*BS2_STR + 512) * 4)

__device__ __forceinline__ void gemm_core_f16(
    const float* __restrict__ A, const float* __restrict__ B,
    int K, int ldb, int row0, int col0,
    float* SgA, float* SgB, unsigned* As2, unsigned* Bs2, float acc[4][4][4])
{
    int tid = threadIdx.x;
    int lane = tid & 31;
    int wi = tid >> 5;
    int g = lane >> 2;
    int t = lane & 3;
    int warp_m = (wi & 1) * 64;
    int warp_n = (wi >> 1) * 16;

    unsigned sga_u = (unsigned)__cvta_generic_to_shared(SgA);
    unsigned sgb_u = (unsigned)__cvta_generic_to_shared(SgB);

    const int nsteps = K >> 5;

#define GEMM_ISSUE(s, buf) do {                                               \
        int k0_ = (s) * 32;                                                   \
        unsigned a_base = sga_u + (buf) * (SGA_ELEMS * 4);                    \
        unsigned b_base = sgb_u + (buf) * (SGB_ELEMS * 4);                    \
        _Pragma("unroll")                                                     \
        for (int it = 0; it < 4; it++) {                                      \
            int id = tid + it * 256;                                          \
            int ar = id >> 3, ac = (id & 7) * 4;                              \
            cp_async16(a_base + (ar * 32 + ac) * 4,                           \
                       A + (size_t)(row0 + ar) * K + k0_ + ac);               \
            int br = id >> 5, bc = (id & 31) * 4;                             \
            cp_async16(b_base + (br * 128 + bc) * 4,                          \
                       B + (size_t)(k0_ + br) * ldb + col0 + bc);             \
        }                                                                     \
        CP_COMMIT();                                                          \
    } while (0)

    GEMM_ISSUE(0, 0);
    GEMM_ISSUE(1, 1);

    for (int s = 0; s < nsteps; s++) {
        int buf = s & 1;
        CP_WAIT(1);
        __syncthreads();

        // convert staging fp32 -> half2 mma buffers
        {
            float* sa = SgA + buf * SGA_ELEMS;
            float* sb = SgB + buf * SGB_ELEMS;
#pragma unroll
            for (int it = 0; it < 4; it++) {
                int id = tid + it * 256;
                int ar = id >> 3, ac = (id & 7) * 4;
                float4 a4 = *(float4*)(sa + ar * 32 + ac);
                uint2 au = make_uint2(pack_h2(a4.x, a4.y), pack_h2(a4.z, a4.w));
                *(uint2*)(As2 + ar * AS2_STR + (ac >> 1)) = au;
            }
#pragma unroll
            for (int it = 0; it < 2; it++) {
                int id = tid + it * 256;
                int kk = id >> 5, c = (id & 31) * 4;
                float4 r0 = *(float4*)(sb + (2 * kk) * 128 + c);
                float4 r1 = *(float4*)(sb + (2 * kk + 1) * 128 + c);
                uint4 bu = make_uint4(pack_h2(r0.x, r1.x), pack_h2(r0.y, r1.y),
                                      pack_h2(r0.z, r1.z), pack_h2(r0.w, r1.w));
                *(uint4*)(Bs2 + kk * BS2_STR + c) = bu;
            }
        }
        __syncthreads();

        if (s + 2 < nsteps) GEMM_ISSUE(s + 2, buf);
        else CP_COMMIT();

        // compute: 2 k16 sub-blocks, 16 mma each
#pragma unroll
        for (int ks = 0; ks < 2; ks++) {
            unsigned af[4][4], bf[4][2];
#pragma unroll
            for (int mi = 0; mi < 4; mi++) {
                int mb = warp_m + mi * 16;
                af[mi][0] = As2[(mb + g) * AS2_STR + ks * 8 + t];
                af[mi][1] = As2[(mb + g + 8) * AS2_STR + ks * 8 + t];
                af[mi][2] = As2[(mb + g) * AS2_STR + ks * 8 + t + 4];
                af[mi][3] = As2[(mb + g + 8) * AS2_STR + ks * 8 + t + 4];
            }
#pragma unroll
            for (int nj = 0; nj < 4; nj++) {
                int noff = (nj & 1) * 8 + (nj >> 1) * 64;   // {0,8,64,72}
                int cb = warp_n + noff + g;
                bf[nj][0] = Bs2[(ks * 8 + t) * BS2_STR + cb];
                bf[nj][1] = Bs2[(ks * 8 + t + 4) * BS2_STR + cb];
            }
#pragma unroll
            for (int mi = 0; mi < 4; mi++)
#pragma unroll
                for (int nj = 0; nj < 4; nj++)
                    mma_f16(acc[mi][nj], af[mi], bf[nj][0], bf[nj][1]);
        }
    }
#undef GEMM_ISSUE
}

// ---------------------------------------------------------------------------
// Fused QKV GEMM (fp16 mma) + per-head RMSNorm + RoPE epilogue for Q/K
// ---------------------------------------------------------------------------
__global__ __launch_bounds__(256, 2) void qkv_f16_kernel(
    const float* __restrict__ x,
    const float* __restrict__ Wq, const float* __restrict__ Wk,
    const float* __restrict__ Wv,
    const float* __restrict__ qw, const float* __restrict__ kw)
{
    extern __shared__ unsigned dsm[];
    float* SgA = (float*)dsm;
    float* SgB = SgA + 2 * SGA_ELEMS;
    unsigned* As2 = (unsigned*)(SgB + 2 * SGB_ELEMS);
    unsigned* Bs2 = As2 + 128 * AS2_STR;
    float (*sred)[4] = (float(*)[4])(Bs2 + 16 * BS2_STR);

    int bx = blockIdx.x;
    const float* B; float* C; const float* w; int ldb, col0, donorm;
    if (bx < 16)      { B = Wq; C = g_q; ldb = Q_OUT;  col0 = bx * 128;        donorm = 1; w = qw; }
    else if (bx < 24) { B = Wk; C = g_k; ldb = KV_OUT; col0 = (bx - 16) * 128; donorm = 1; w = kw; }
    else              { B = Wv; C = g_v; ldb = KV_OUT; col0 = (bx - 24) * 128; donorm = 0; w = qw; }

    int row0 = blockIdx.y * 128;

    float acc[4][4][4];
#pragma unroll
    for (int mi = 0; mi < 4; mi++)
#pragma unroll
        for (int nj = 0; nj < 4; nj++)
#pragma unroll
            for (int c = 0; c < 4; c++) acc[mi][nj][c] = 0.0f;

    gemm_core_f16(x, B, HIDDEN, ldb, row0, col0, SgA, SgB, As2, Bs2, acc);

    int tid = threadIdx.x;
    int lane = tid & 31;
    int wi = tid >> 5;
    int g = lane >> 2;
    int t = lane & 3;
    int warp_m = (wi & 1) * 64;
    int warp_n = (wi >> 1) * 16;
    int wq = wi >> 1;

    if (donorm) {
        float ssl[4][2];
#pragma unroll
        for (int mi = 0; mi < 4; mi++)
#pragma unroll
            for (int hf = 0; hf < 2; hf++) {
                float s = 0.0f;
#pragma unroll
                for (int nj = 0; nj < 4; nj++)
#pragma unroll
                    for (int b2 = 0; b2 < 2; b2++) {
                        float v = acc[mi][nj][hf * 2 + b2];
                        s = fmaf(v, v, s);
                    }
                s += __shfl_xor_sync(0xffffffffu, s, 1);
                s += __shfl_xor_sync(0xffffffffu, s, 2);
                ssl[mi][hf] = s;
            }
        __syncthreads();
        if (t == 0) {
#pragma unroll
            for (int mi = 0; mi < 4; mi++)
#pragma unroll
                for (int hf = 0; hf < 2; hf++)
                    sred[warp_m + mi * 16 + g + 8 * hf][wq] = ssl[mi][hf];
        }
        __syncthreads();

        float wv[4][2];
#pragma unroll
        for (int nj = 0; nj < 4; nj++) {
            int noff = (nj & 1) * 8 + (nj >> 1) * 64;
            wv[nj][0] = w[warp_n + noff + 2 * t];
            wv[nj][1] = w[warp_n + noff + 2 * t + 1];
        }

#pragma unroll
        for (int mi = 0; mi < 4; mi++)
#pragma unroll
            for (int hf = 0; hf < 2; hf++) {
                int row = warp_m + mi * 16 + g + 8 * hf;
                float tot = sred[row][0] + sred[row][1] + sred[row][2] + sred[row][3];
                float r = rsqrtf(tot * (1.0f / 128.0f) + 1e-6f);
                int token = row0 + row;
                int tp = token & (SEQ - 1);

                float nv[4][2];
#pragma unroll
                for (int nj = 0; nj < 4; nj++)
#pragma unroll
                    for (int b2 = 0; b2 < 2; b2++)
                        nv[nj][b2] = acc[mi][nj][hf * 2 + b2] * r * wv[nj][b2];

#pragma unroll
                for (int nj = 0; nj < 4; nj++) {
                    int noff = (nj & 1) * 8 + (nj >> 1) * 64;
                    int ci = warp_n + (nj & 1) * 8 + 2 * t;   // d & 63
                    float c0 = g_cosT[tp * 64 + ci];
                    float s0 = g_sinT[tp * 64 + ci];
                    float c1 = g_cosT[tp * 64 + ci + 1];
                    float s1 = g_sinT[tp * 64 + ci + 1];
                    float rot0 = (nj < 2) ? -nv[nj + 2][0] : nv[nj - 2][0];
                    float rot1 = (nj < 2) ? -nv[nj + 2][1] : nv[nj - 2][1];
                    float2 o2 = make_float2(nv[nj][0] * c0 + rot0 * s0,
                                            nv[nj][1] * c1 + rot1 * s1);
                    *(float2*)(C + (size_t)token * ldb + col0 + warp_n + noff + 2 * t) = o2;
                }
            }
    } else {
#pragma unroll
        for (int mi = 0; mi < 4; mi++)
#pragma unroll
            for (int hf = 0; hf < 2; hf++) {
                int row = warp_m + mi * 16 + g + 8 * hf;
                int token = row0 + row;
#pragma unroll
                for (int nj = 0; nj < 4; nj++) {
                    int noff = (nj & 1) * 8 + (nj >> 1) * 64;
                    float2 o2 = make_float2(acc[mi][nj][hf * 2 + 0],
                                            acc[mi][nj][hf * 2 + 1]);
                    *(float2*)(C + (size_t)token * ldb + col0 + warp_n + noff + 2 * t) = o2;
                }
            }
    }
}

// ---------------------------------------------------------------------------
// Wo GEMM (fp16 mma)
// ---------------------------------------------------------------------------
__global__ __launch_bounds__(256, 2) void wo_f16_kernel(
    const float* __restrict__ A, const float* __restrict__ B,
    float* __restrict__ C)
{
    extern __shared__ unsigned dsm[];
    float* SgA = (float*)dsm;
    float* SgB = SgA + 2 * SGA_ELEMS;
    unsigned* As2 = (unsigned*)(SgB + 2 * SGB_ELEMS);
    unsigned* Bs2 = As2 + 128 * AS2_STR;

    int row0 = blockIdx.y * 128;
    int col0 = blockIdx.x * 128;

    float acc[4][4][4];
#pragma unroll
    for (int mi = 0; mi < 4; mi++)
#pragma unroll
        for (int nj = 0; nj < 4; nj++)
#pragma unroll
            for (int c = 0; c < 4; c++) acc[mi][nj][c] = 0.0f;

    gemm_core_f16(A, B, Q_OUT, HIDDEN, row0, col0, SgA, SgB, As2, Bs2, acc);

    int tid = threadIdx.x;
    int lane = tid & 31;
    int wi = tid >> 5;
    int g = lane >> 2;
    int t = lane & 3;
    int warp_m = (wi & 1) * 64;
    int warp_n = (wi >> 1) * 16;

#pragma unroll
    for (int mi = 0; mi < 4; mi++)
#pragma unroll
        for (int hf = 0; hf < 2; hf++) {
            int row = row0 + warp_m + mi * 16 + g + 8 * hf;
#pragma unroll
            for (int nj = 0; nj < 4; nj++) {
                int noff = (nj & 1) * 8 + (nj >> 1) * 64;
                float2 o2 = make_float2(acc[mi][nj][hf * 2 + 0],
                                        acc[mi][nj][hf * 2 + 1]);
                *(float2*)(C + (size_t)row * HIDDEN + col0 + warp_n + noff + 2 * t) = o2;
            }
        }
}

// ---------------------------------------------------------------------------
// Flash attention, fp16 mma, causal, GQA rep=2, cp.async K/V staging.
// Ks2[dd][key]: half2 pairs along d   (64 x 136)
// Vs2[kk][d]  : half2 pairs along key (32 x 136)
// P stays in registers (fp16 A-fragment layout == softmax register layout).
// ---------------------------------------------------------------------------
#define KS2_STR 136
#define VS2_STR 136
#define FA_SMEM ((2*64*128) * 4 + (64*KS2_STR + 32*VS2_STR) * 4)

__global__ __launch_bounds__(256, 1) void flash_f16_kernel(
    const float* __restrict__ Q, const float* __restrict__ K,
    const float* __restrict__ V, float* __restrict__ O)
{
    extern __shared__ unsigned smu[];
    float* SgK = (float*)smu;                  // [64][128] fp32 staging
    float* SgV = SgK + 64 * 128;               // [64][128]
    unsigned* Ks2 = (unsigned*)(SgV + 64 * 128);   // [64][136] half2
    unsigned* Vs2 = Ks2 + 64 * KS2_STR;            // [32][136] half2

    unsigned sgk_u = (unsigned)__cvta_generic_to_shared(SgK);
    unsigned sgv_u = (unsigned)__cvta_generic_to_shared(SgV);

    int qt = gridDim.x - 1 - blockIdx.x;   // big tiles first
    int h  = blockIdx.y;
    int b  = blockIdx.z;
    int kvh = h >> 1;
    int q0 = qt * 128;

    int tid = threadIdx.x;
    int w = tid >> 5;
    int lane = tid & 31;
    int g = lane >> 2;
    int t = lane & 3;

    int row0 = w * 16 + g;
    int row1 = row0 + 8;
    int qrow0 = q0 + row0;
    int qrow1 = q0 + row1;

    const float* Kbase = K + ((size_t)b * SEQ * NKV + kvh) * HDIM;
    const float* Vbase = V + ((size_t)b * SEQ * NKV + kvh) * HDIM;

    int nkt = 2 * qt + 2;

#define FA_ISSUE(kt_) do {                                                    \
        const float* kg_ = Kbase + (size_t)(kt_) * 64 * KV_OUT;               \
        const float* vg_ = Vbase + (size_t)(kt_) * 64 * KV_OUT;               \
        _Pragma("unroll")                                                     \
        for (int it = 0; it < 8; it++) {                                      \
            int idx = tid + it * 256;                                         \
            int r_ = idx >> 5, c_ = (idx & 31) * 4;                           \
            cp_async16(sgk_u + (r_ * 128 + c_) * 4, kg_ + (size_t)r_ * KV_OUT + c_); \
            cp_async16(sgv_u + (r_ * 128 + c_) * 4, vg_ + (size_t)r_ * KV_OUT + c_); \
        }                                                                     \
        CP_COMMIT();                                                          \
    } while (0)

    FA_ISSUE(0);

    // Q fragments (fp16, pre-scaled) in registers — overlaps cp.async
    unsigned qf[8][4];
    {
        const float scale = 0.08838834764831845f;  // 1/sqrt(128)
        const float* qb0 = Q + ((size_t)(b * SEQ + qrow0) * NQ + h) * HDIM;
        const float* qb1 = Q + ((size_t)(b * SEQ + qrow1) * NQ + h) * HDIM;
#pragma unroll
        for (int ks = 0; ks < 8; ks++) {
            float2 x0 = *(const float2*)(qb0 + ks * 16 + 2 * t);
            float2 x1 = *(const float2*)(qb1 + ks * 16 + 2 * t);
            float2 x2 = *(const float2*)(qb0 + ks * 16 + 2 * t + 8);
            float2 x3 = *(const float2*)(qb1 + ks * 16 + 2 * t + 8);
            qf[ks][0] = pack_h2(x0.x * scale, x0.y * scale);
            qf[ks][1] = pack_h2(x1.x * scale, x1.y * scale);
            qf[ks][2] = pack_h2(x2.x * scale, x2.y * scale);
            qf[ks][3] = pack_h2(x3.x * scale, x3.y * scale);
        }
    }

    float of[16][4];
#pragma unroll
    for (int j = 0; j < 16; j++)
#pragma unroll
        for (int c = 0; c < 4; c++) of[j][c] = 0.0f;
    float m0 = -1e30f, m1 = -1e30f, l0 = 0.0f, l1 = 0.0f;

    for (int kt = 0; kt < nkt; kt++) {
        int k0 = kt * 64;

        CP_WAIT(0);
        __syncthreads();

        // convert staging fp32 -> half2 layouts
        // K: Ks2[dd][key] pairs along d
#pragma unroll
        for (int it = 0; it < 8; it++) {
            int idx = tid + it * 256;
            int r = idx >> 5, c = (idx & 31) * 4;
            float4 k4 = *(float4*)(SgK + r * 128 + c);
            Ks2[(c >> 1) * KS2_STR + r]       = pack_h2(k4.x, k4.y);
            Ks2[((c >> 1) + 1) * KS2_STR + r] = pack_h2(k4.z, k4.w);
        }
        // V: Vs2[kk][d] pairs along key
#pragma unroll
        for (int it = 0; it < 4; it++) {
            int idx = tid + it * 256;
            int kk = idx >> 5, c = (idx & 31) * 4;
            float4 r0 = *(float4*)(SgV + (2 * kk) * 128 + c);
            float4 r1 = *(float4*)(SgV + (2 * kk + 1) * 128 + c);
            uint4 vu = make_uint4(pack_h2(r0.x, r1.x), pack_h2(r0.y, r1.y),
                                  pack_h2(r0.z, r1.z), pack_h2(r0.w, r1.w));
            *(uint4*)(Vs2 + kk * VS2_STR + c) = vu;
        }
        __syncthreads();

        if (kt + 1 < nkt) FA_ISSUE(kt + 1);

        // fully-masked warps skip compute
        if (k0 > q0 + w * 16 + 15) continue;

        // --- S = Q @ K^T : 8 d-blocks x 8 key-groups ---
        float sf[8][4];
#pragma unroll
        for (int j = 0; j < 8; j++)
#pragma unroll
            for (int c = 0; c < 4; c++) sf[j][c] = 0.0f;

#pragma unroll
        for (int ks = 0; ks < 8; ks++) {
#pragma unroll
            for (int j = 0; j < 8; j++) {
                unsigned b0 = Ks2[(ks * 8 + t) * KS2_STR + j * 8 + g];
                unsigned b1 = Ks2[(ks * 8 + t + 4) * KS2_STR + j * 8 + g];
                mma_f16(sf[j], qf[ks], b0, b1);
            }
        }

        if (kt >= nkt - 2) {
#pragma unroll
            for (int j = 0; j < 8; j++) {
                int kg0 = k0 + j * 8 + 2 * t;
                if (kg0 > qrow0)     sf[j][0] = -1e30f;
                if (kg0 + 1 > qrow0) sf[j][1] = -1e30f;
                if (kg0 > qrow1)     sf[j][2] = -1e30f;
                if (kg0 + 1 > qrow1) sf[j][3] = -1e30f;
            }
        }

        // --- online softmax ---
        float mt0 = -1e30f, mt1 = -1e30f;
#pragma unroll
        for (int j = 0; j < 8; j++) {
            mt0 = fmaxf(mt0, fmaxf(sf[j][0], sf[j][1]));
            mt1 = fmaxf(mt1, fmaxf(sf[j][2], sf[j][3]));
        }
        mt0 = fmaxf(mt0, __shfl_xor_sync(0xffffffffu, mt0, 1));
        mt0 = fmaxf(mt0, __shfl_xor_sync(0xffffffffu, mt0, 2));
        mt1 = fmaxf(mt1, __shfl_xor_sync(0xffffffffu, mt1, 1));
        mt1 = fmaxf(mt1, __shfl_xor_sync(0xffffffffu, mt1, 2));

        float mn0 = fmaxf(m0, mt0), mn1 = fmaxf(m1, mt1);
        float corr0 = __expf(m0 - mn0), corr1 = __expf(m1 - mn1);
        m0 = mn0; m1 = mn1;

        float rs0 = 0.0f, rs1 = 0.0f;
#pragma unroll
        for (int j = 0; j < 8; j++) {
            sf[j][0] = __expf(sf[j][0] - mn0);
            sf[j][1] = __expf(sf[j][1] - mn0);
            sf[j][2] = __expf(sf[j][2] - mn1);
            sf[j][3] = __expf(sf[j][3] - mn1);
            rs0 += sf[j][0] + sf[j][1];
            rs1 += sf[j][2] + sf[j][3];
        }
        rs0 += __shfl_xor_sync(0xffffffffu, rs0, 1);
        rs0 += __shfl_xor_sync(0xffffffffu, rs0, 2);
        rs1 += __shfl_xor_sync(0xffffffffu, rs1, 1);
        rs1 += __shfl_xor_sync(0xffffffffu, rs1, 2);
        l0 = l0 * corr0 + rs0;
        l1 = l1 * corr1 + rs1;

#pragma unroll
        for (int j = 0; j < 16; j++) {
            of[j][0] *= corr0; of[j][1] *= corr0;
            of[j][2] *= corr1; of[j][3] *= corr1;
        }

        // --- P fragments directly from softmax registers ---
        unsigned pf[4][4];
#pragma unroll
        for (int ks = 0; ks < 4; ks++) {
            pf[ks][0] = pack_h2(sf[2 * ks][0],     sf[2 * ks][1]);
            pf[ks][1] = pack_h2(sf[2 * ks][2],     sf[2 * ks][3]);
            pf[ks][2] = pack_h2(sf[2 * ks + 1][0], sf[2 * ks + 1][1]);
            pf[ks][3] = pack_h2(sf[2 * ks + 1][2], sf[2 * ks + 1][3]);
        }

        // --- O += P @ V : 4 key-blocks x 16 d-groups ---
#pragma unroll
        for (int ks = 0; ks < 4; ks++) {
#pragma unroll
            for (int j = 0; j < 16; j++) {
                unsigned b0 = Vs2[(ks * 8 + t) * VS2_STR + j * 8 + g];
                unsigned b1 = Vs2[(ks * 8 + t + 4) * VS2_STR + j * 8 + g];
                mma_f16(of[j], pf[ks], b0, b1);
            }
        }
    }
#undef FA_ISSUE

    float inv0 = 1.0f / l0, inv1 = 1.0f / l1;
    float* og0 = O + ((size_t)(b * SEQ + qrow0) * NQ + h) * HDIM;
    float* og1 = O + ((size_t)(b * SEQ + qrow1) * NQ + h) * HDIM;
#pragma unroll
    for (int j = 0; j < 16; j++) {
        float2 v0 = make_float2(of[j][0] * inv0, of[j][1] * inv0);
        float2 v1 = make_float2(of[j][2] * inv1, of[j][3] * inv1);
        *(float2*)(og0 + j * 8 + 2 * t) = v0;
        *(float2*)(og1 + j * 8 + 2 * t) = v1;
    }
}

// ---------------------------------------------------------------------------
// Launch
// ---------------------------------------------------------------------------
extern "C" void kernel_launch(void* const* d_in, const int* in_sizes, int n_in,
                              void* d_out, int out_size)
{
    const float* x  = (const float*)d_in[0];
    const float* Wq = (const float*)d_in[1];
    const float* Wk = (const float*)d_in[2];
    const float* Wv = (const float*)d_in[3];
    const float* Wo = (const float*)d_in[4];
    const float* qw = (const float*)d_in[5];
    const float* kw = (const float*)d_in[6];
    float* out = (float*)d_out;

    float *pq, *pk, *pv, *po;
    cudaGetSymbolAddress((void**)&pq, g_q);
    cudaGetSymbolAddress((void**)&pk, g_k);
    cudaGetSymbolAddress((void**)&pv, g_v);
    cudaGetSymbolAddress((void**)&po, g_o);

    cudaFuncSetAttribute(qkv_f16_kernel,
                         cudaFuncAttributeMaxDynamicSharedMemorySize, GEMM_SMEM);
    cudaFuncSetAttribute(wo_f16_kernel,
                         cudaFuncAttributeMaxDynamicSharedMemorySize, GEMM_SMEM);
    cudaFuncSetAttribute(flash_f16_kernel,
                         cudaFuncAttributeMaxDynamicSharedMemorySize, FA_SMEM);

    // RoPE tables
    rope_table_kernel<<<SEQ, 64>>>();

    // Fused QKV projection (fp16 mma) + RMSNorm + RoPE epilogue
    qkv_f16_kernel<<<dim3(32, TOKENS / 128), 256, GEMM_SMEM>>>(x, Wq, Wk, Wv, qw, kw);

    // Flash attention (fp16 mma, cp.async pipelined, P in registers)
    flash_f16_kernel<<<dim3(SEQ / 128, NQ, BATCH), 256, FA_SMEM>>>(pq, pk, pv, po);

    // Output projection (fp16 mma)
    wo_f16_kernel<<<dim3(HIDDEN / 128, TOKENS / 128), 256, GEMM_SMEM>>>(po, Wo, out);
}

// round 6
// speedup vs baseline: 8.8513x; 1.4132x over previous
#include <cuda_runtime.h>
#include <cuda_fp16.h>
#include <math.h>

// ---------------------------------------------------------------------------
// Problem constants
// ---------------------------------------------------------------------------
#define BATCH   2
#define SEQ     2048
#define HIDDEN  1024
#define Q_OUT   2048
#define KV_OUT  1024
#define HDIM    128
#define NQ      16
#define NKV     8
#define TOKENS  (BATCH*SEQ)          // 4096

// ---------------------------------------------------------------------------
// Scratch (device globals; no allocation allowed). All half2-packed as uint.
// ---------------------------------------------------------------------------
__device__ unsigned g_xh [TOKENS * 512];            // x pairs along k      [m][kk]
__device__ unsigned g_wqh[512 * Q_OUT];             // Wq pairs along k     [kk][n]
__device__ unsigned g_wkh[512 * KV_OUT];
__device__ unsigned g_wvh[512 * KV_OUT];
__device__ unsigned g_woh[1024 * HIDDEN];
__device__ unsigned g_qh [TOKENS * 1024];           // q (scaled) pairs along d  [token][h*64+dd]
__device__ unsigned g_kTh[(size_t)BATCH * NKV * 64 * SEQ];        // [b][kvh][dd][token]
__device__ unsigned g_vTh[(size_t)BATCH * NKV * (SEQ/2) * 128];   // [b][kvh][kk][d]
__device__ unsigned g_oh [TOKENS * 1024];           // attn out pairs along d [token][h*64+dd]
__device__ float g_cosT[SEQ * 64];
__device__ float g_sinT[SEQ * 64];

// ---------------------------------------------------------------------------
// helpers
// ---------------------------------------------------------------------------
__device__ __forceinline__ unsigned pack_h2(float lo, float hi) {
    unsigned u;
    asm("cvt.rn.f16x2.f32 %0, %2, %1;" : "=r"(u) : "f"(lo), "f"(hi));
    return u;
}

__device__ __forceinline__ void mma_f16(float* c, const unsigned* a,
                                        unsigned b0, unsigned b1) {
    asm("mma.sync.aligned.m16n8k16.row.col.f32.f16.f16.f32 "
        "{%0,%1,%2,%3}, {%4,%5,%6,%7}, {%8,%9}, {%0,%1,%2,%3};"
        : "+f"(c[0]), "+f"(c[1]), "+f"(c[2]), "+f"(c[3])
        : "r"(a[0]), "r"(a[1]), "r"(a[2]), "r"(a[3]), "r"(b0), "r"(b1));
}

__device__ __forceinline__ void cp_async16(unsigned dst_smem, const void* src) {
    asm volatile("cp.async.cg.shared.global [%0], [%1], 16;\n"
                 :: "r"(dst_smem), "l"(src));
}
#define CP_COMMIT()  asm volatile("cp.async.commit_group;\n" ::: "memory")
#define CP_WAIT(N)   asm volatile("cp.async.wait_group %0;\n" :: "n"(N) : "memory")

// ---------------------------------------------------------------------------
// RoPE table
// ---------------------------------------------------------------------------
__global__ void rope_table_kernel() {
    int t = blockIdx.x;
    int j = threadIdx.x;   // 0..63
    float e = (float)j * (1.0f / 64.0f);
    float inv = exp2f(-e * 13.287712379549449f);  // log2(10000)
    float a = (float)t * inv;
    float s, c;
    sincosf(a, &s, &c);
    g_cosT[t * 64 + j] = c;
    g_sinT[t * 64 + j] = s;
}

// ---------------------------------------------------------------------------
// Prep: pack x (pairs along k, row-major adjacency)
// ---------------------------------------------------------------------------
__global__ void pack_x_kernel(const float* __restrict__ x) {
    int id = blockIdx.x * 256 + threadIdx.x;     // < TOKENS*512
    g_xh[id] = pack_h2(x[2 * id], x[2 * id + 1]);
}

// ---------------------------------------------------------------------------
// Prep: pack all weights into [kk][n] pair layout (one fused launch)
// segments: Wq 1M, Wk 0.5M, Wv 0.5M, Wo 1M uints
// ---------------------------------------------------------------------------
__global__ void pack_w_kernel(const float* __restrict__ Wq,
                              const float* __restrict__ Wk,
                              const float* __restrict__ Wv,
                              const float* __restrict__ Wo) {
    int id = blockIdx.x * 256 + threadIdx.x;
    const float* src; unsigned* dst; int N;
    if (id < 1048576)       { src = Wq; dst = g_wqh; N = 2048; }
    else if (id < 1572864)  { id -= 1048576; src = Wk; dst = g_wkh; N = 1024; }
    else if (id < 2097152)  { id -= 1572864; src = Wv; dst = g_wvh; N = 1024; }
    else                    { id -= 2097152; src = Wo; dst = g_woh; N = 1024; }
    int kk = id / N, n = id - kk * N;
    dst[id] = pack_h2(src[(size_t)(2 * kk) * N + n],
                      src[(size_t)(2 * kk + 1) * N + n]);
}

// ---------------------------------------------------------------------------
// fp16 GEMM core v2: inputs already half2-packed; cp.async lands directly in
// mma-layout smem (triple-buffered). 128x128 tile, BK=32 (16 half2).
//   As2[m][kk] stride 20, Bs2[kk][n] stride 136 (both conflict-free frags)
// ---------------------------------------------------------------------------
#define AS2_STR 20
#define BS2_STR 136
#define AS2_BUF (128 * AS2_STR)     // 2560 uints
#define BS2_BUF (16 * BS2_STR)      // 2176 uints
#define GEMM_SMEM ((3 * AS2_BUF + 3 * BS2_BUF + 512) * 4)

__device__ __forceinline__ void gemm_core_h(
    const unsigned* __restrict__ Ah, const unsigned* __restrict__ Bh,
    int K2, int ldb, int row0, int col0,
    unsigned* As2, unsigned* Bs2, float acc[4][4][4])
{
    int tid = threadIdx.x;
    int lane = tid & 31;
    int wi = tid >> 5;
    int g = lane >> 2;
    int t = lane & 3;
    int warp_m = (wi & 1) * 64;
    int warp_n = (wi >> 1) * 16;

    unsigned as_u = (unsigned)__cvta_generic_to_shared(As2);
    unsigned bs_u = (unsigned)__cvta_generic_to_shared(Bs2);

    const int nsteps = K2 >> 4;

#define GEMM_ISSUE(s, buf) do {                                               \
        int kk0_ = (s) * 16;                                                  \
        unsigned a_base = as_u + (buf) * (AS2_BUF * 4);                       \
        unsigned b_base = bs_u + (buf) * (BS2_BUF * 4);                       \
        _Pragma("unroll")                                                     \
        for (int it = 0; it < 2; it++) {                                      \
            int id = tid + it * 256;                                          \
            int ar = id >> 2, ac = (id & 3) * 4;                              \
            cp_async16(a_base + (ar * AS2_STR + ac) * 4,                      \
                       Ah + (size_t)(row0 + ar) * K2 + kk0_ + ac);            \
            int br = id >> 5, bc = (id & 31) * 4;                             \
            cp_async16(b_base + (br * BS2_STR + bc) * 4,                      \
                       Bh + (size_t)(kk0_ + br) * ldb + col0 + bc);           \
        }                                                                     \
        CP_COMMIT();                                                          \
    } while (0)

    GEMM_ISSUE(0, 0);
    GEMM_ISSUE(1, 1);

    int buf = 0;
    for (int s = 0; s < nsteps; s++) {
        CP_WAIT(1);
        __syncthreads();

        if (s + 2 < nsteps) {
            int nb = buf + 2; if (nb >= 3) nb -= 3;
            GEMM_ISSUE(s + 2, nb);
        } else {
            CP_COMMIT();
        }

        unsigned* Ab = As2 + buf * AS2_BUF;
        unsigned* Bb = Bs2 + buf * BS2_BUF;
#pragma unroll
        for (int ks = 0; ks < 2; ks++) {
            unsigned af[4][4], bf[4][2];
#pragma unroll
            for (int mi = 0; mi < 4; mi++) {
                int mb = warp_m + mi * 16;
                af[mi][0] = Ab[(mb + g) * AS2_STR + ks * 8 + t];
                af[mi][1] = Ab[(mb + g + 8) * AS2_STR + ks * 8 + t];
                af[mi][2] = Ab[(mb + g) * AS2_STR + ks * 8 + t + 4];
                af[mi][3] = Ab[(mb + g + 8) * AS2_STR + ks * 8 + t + 4];
            }
#pragma unroll
            for (int nj = 0; nj < 4; nj++) {
                int noff = (nj & 1) * 8 + (nj >> 1) * 64;   // {0,8,64,72}
                int cb = warp_n + noff + g;
                bf[nj][0] = Bb[(ks * 8 + t) * BS2_STR + cb];
                bf[nj][1] = Bb[(ks * 8 + t + 4) * BS2_STR + cb];
            }
#pragma unroll
            for (int mi = 0; mi < 4; mi++)
#pragma unroll
                for (int nj = 0; nj < 4; nj++)
                    mma_f16(acc[mi][nj], af[mi], bf[nj][0], bf[nj][1]);
        }

        buf++; if (buf == 3) buf = 0;
    }
#undef GEMM_ISSUE
}

// ---------------------------------------------------------------------------
// Fused QKV GEMM + RMSNorm + RoPE; writes flash-ready half layouts:
//   Q: g_qh scaled pairs-along-d; K: g_kTh [b][kvh][dd][token];
//   V: g_vTh [b][kvh][tok/2][d] (token-paired via shfl)
// grid (32, TOKENS/128)
// ---------------------------------------------------------------------------
__global__ __launch_bounds__(256, 2) void qkv_h_kernel(
    const float* __restrict__ qw, const float* __restrict__ kw)
{
    extern __shared__ unsigned dsm[];
    unsigned* As2 = dsm;
    unsigned* Bs2 = As2 + 3 * AS2_BUF;
    float (*sred)[4] = (float(*)[4])(Bs2 + 3 * BS2_BUF);

    int bx = blockIdx.x;
    const unsigned* Bh; const float* w; int ldb, col0, mode, head;
    if (bx < 16)      { Bh = g_wqh; ldb = Q_OUT;  col0 = bx * 128;        mode = 0; head = bx;      w = qw; }
    else if (bx < 24) { Bh = g_wkh; ldb = KV_OUT; col0 = (bx - 16) * 128; mode = 1; head = bx - 16; w = kw; }
    else              { Bh = g_wvh; ldb = KV_OUT; col0 = (bx - 24) * 128; mode = 2; head = bx - 24; w = qw; }

    int row0 = blockIdx.y * 128;

    float acc[4][4][4];
#pragma unroll
    for (int mi = 0; mi < 4; mi++)
#pragma unroll
        for (int nj = 0; nj < 4; nj++)
#pragma unroll
            for (int c = 0; c < 4; c++) acc[mi][nj][c] = 0.0f;

    gemm_core_h(g_xh, Bh, 512, ldb, row0, col0, As2, Bs2, acc);

    int tid = threadIdx.x;
    int lane = tid & 31;
    int wi = tid >> 5;
    int g = lane >> 2;
    int t = lane & 3;
    int warp_m = (wi & 1) * 64;
    int warp_n = (wi >> 1) * 16;
    int wq = wi >> 1;

    if (mode != 2) {
        // --- RMSNorm sum of squares ---
        float ssl[4][2];
#pragma unroll
        for (int mi = 0; mi < 4; mi++)
#pragma unroll
            for (int hf = 0; hf < 2; hf++) {
                float s = 0.0f;
#pragma unroll
                for (int nj = 0; nj < 4; nj++)
#pragma unroll
                    for (int b2 = 0; b2 < 2; b2++) {
                        float v = acc[mi][nj][hf * 2 + b2];
                        s = fmaf(v, v, s);
                    }
                s += __shfl_xor_sync(0xffffffffu, s, 1);
                s += __shfl_xor_sync(0xffffffffu, s, 2);
                ssl[mi][hf] = s;
            }
        __syncthreads();
        if (t == 0) {
#pragma unroll
            for (int mi = 0; mi < 4; mi++)
#pragma unroll
                for (int hf = 0; hf < 2; hf++)
                    sred[warp_m + mi * 16 + g + 8 * hf][wq] = ssl[mi][hf];
        }
        __syncthreads();

        float wv[4][2];
#pragma unroll
        for (int nj = 0; nj < 4; nj++) {
            int noff = (nj & 1) * 8 + (nj >> 1) * 64;
            wv[nj][0] = w[warp_n + noff + 2 * t];
            wv[nj][1] = w[warp_n + noff + 2 * t + 1];
        }

        const float qscale = 0.08838834764831845f;  // 1/sqrt(128), Q only

#pragma unroll
        for (int mi = 0; mi < 4; mi++)
#pragma unroll
            for (int hf = 0; hf < 2; hf++) {
                int row = warp_m + mi * 16 + g + 8 * hf;
                float tot = sred[row][0] + sred[row][1] + sred[row][2] + sred[row][3];
                float r = rsqrtf(tot * (1.0f / 128.0f) + 1e-6f);
                int token = row0 + row;
                int tp = token & (SEQ - 1);
                int bb = token >> 11;

                float nv[4][2];
#pragma unroll
                for (int nj = 0; nj < 4; nj++)
#pragma unroll
                    for (int b2 = 0; b2 < 2; b2++)
                        nv[nj][b2] = acc[mi][nj][hf * 2 + b2] * r * wv[nj][b2];

#pragma unroll
                for (int nj = 0; nj < 4; nj++) {
                    int noff = (nj & 1) * 8 + (nj >> 1) * 64;
                    int ci = warp_n + (nj & 1) * 8 + 2 * t;   // d & 63
                    float c0 = g_cosT[tp * 64 + ci];
                    float s0 = g_sinT[tp * 64 + ci];
                    float c1 = g_cosT[tp * 64 + ci + 1];
                    float s1 = g_sinT[tp * 64 + ci + 1];
                    float rot0 = (nj < 2) ? -nv[nj + 2][0] : nv[nj - 2][0];
                    float rot1 = (nj < 2) ? -nv[nj + 2][1] : nv[nj - 2][1];
                    float o0 = nv[nj][0] * c0 + rot0 * s0;
                    float o1 = nv[nj][1] * c1 + rot1 * s1;
                    int dd = (warp_n + noff) / 2 + t;        // pair index in head
                    if (mode == 0) {
                        g_qh[(size_t)token * 1024 + head * 64 + dd] =
                            pack_h2(o0 * qscale, o1 * qscale);
                    } else {
                        g_kTh[((size_t)(bb * NKV + head) * 64 + dd) * SEQ + tp] =
                            pack_h2(o0, o1);
                    }
                }
            }
    } else {
        // --- V: pack pairs along token (lane g even pairs with g+1) ---
#pragma unroll
        for (int mi = 0; mi < 4; mi++)
#pragma unroll
            for (int hf = 0; hf < 2; hf++) {
                int row = warp_m + mi * 16 + g + 8 * hf;
                int token = row0 + row;
                int tp = token & (SEQ - 1);
                int bb = token >> 11;
#pragma unroll
                for (int nj = 0; nj < 4; nj++) {
                    int noff = (nj & 1) * 8 + (nj >> 1) * 64;
                    float v0 = acc[mi][nj][hf * 2 + 0];
                    float v1 = acc[mi][nj][hf * 2 + 1];
                    float n0 = __shfl_down_sync(0xffffffffu, v0, 4);
                    float n1 = __shfl_down_sync(0xffffffffu, v1, 4);
                    if (!(g & 1)) {
                        int d0 = warp_n + noff + 2 * t;
                        uint2 u = make_uint2(pack_h2(v0, n0), pack_h2(v1, n1));
                        *(uint2*)(g_vTh + ((size_t)(bb * NKV + head) * (SEQ/2)
                                           + (tp >> 1)) * 128 + d0) = u;
                    }
                }
            }
    }
}

// ---------------------------------------------------------------------------
// Wo GEMM: A = g_oh (half pairs), B = g_woh; writes fp32 out
// ---------------------------------------------------------------------------
__global__ __launch_bounds__(256, 2) void wo_h_kernel(float* __restrict__ C)
{
    extern __shared__ unsigned dsm[];
    unsigned* As2 = dsm;
    unsigned* Bs2 = As2 + 3 * AS2_BUF;

    int row0 = blockIdx.y * 128;
    int col0 = blockIdx.x * 128;

    float acc[4][4][4];
#pragma unroll
    for (int mi = 0; mi < 4; mi++)
#pragma unroll
        for (int nj = 0; nj < 4; nj++)
#pragma unroll
            for (int c = 0; c < 4; c++) acc[mi][nj][c] = 0.0f;

    gemm_core_h(g_oh, g_woh, 1024, HIDDEN, row0, col0, As2, Bs2, acc);

    int tid = threadIdx.x;
    int lane = tid & 31;
    int wi = tid >> 5;
    int g = lane >> 2;
    int t = lane & 3;
    int warp_m = (wi & 1) * 64;
    int warp_n = (wi >> 1) * 16;

#pragma unroll
    for (int mi = 0; mi < 4; mi++)
#pragma unroll
        for (int hf = 0; hf < 2; hf++) {
            int row = row0 + warp_m + mi * 16 + g + 8 * hf;
#pragma unroll
            for (int nj = 0; nj < 4; nj++) {
                int noff = (nj & 1) * 8 + (nj >> 1) * 64;
                float2 o2 = make_float2(acc[mi][nj][hf * 2 + 0],
                                        acc[mi][nj][hf * 2 + 1]);
                *(float2*)(C + (size_t)row * HIDDEN + col0 + warp_n + noff + 2 * t) = o2;
            }
        }
}

// ---------------------------------------------------------------------------
// Flash attention: all inputs half, cp.async lands directly in mma layouts.
//   K tile: Ks[dd][key] 64x136, V tile: Vs[kk][d] 32x136 (after K rows)
//   Double buffered. Q frags direct from gmem. P stays in registers.
// ---------------------------------------------------------------------------
#define FAS_STR 136
#define FA_BUF (96 * FAS_STR)            // 64 K rows + 32 V rows
#define FA_SMEM (2 * FA_BUF * 4)

__global__ __launch_bounds__(256, 1) void flash_h_kernel()
{
    extern __shared__ unsigned smu[];
    unsigned smu_u = (unsigned)__cvta_generic_to_shared(smu);

    int qt = gridDim.x - 1 - blockIdx.x;   // big tiles first
    int h  = blockIdx.y;
    int b  = blockIdx.z;
    int kvh = h >> 1;
    int q0 = qt * 128;

    int tid = threadIdx.x;
    int w = tid >> 5;
    int lane = tid & 31;
    int g = lane >> 2;
    int t = lane & 3;

    int row0 = w * 16 + g;
    int row1 = row0 + 8;
    int qrow0 = q0 + row0;
    int qrow1 = q0 + row1;

    const unsigned* Kt = g_kTh + (size_t)(b * NKV + kvh) * 64 * SEQ;
    const unsigned* Vt = g_vTh + (size_t)(b * NKV + kvh) * (SEQ/2) * 128;

    int nkt = 2 * qt + 2;

#define FA_ISSUE(kt_, bf_) do {                                               \
        unsigned base = smu_u + (bf_) * (FA_BUF * 4);                         \
        _Pragma("unroll")                                                     \
        for (int it = 0; it < 4; it++) {                                      \
            int id = tid + it * 256;                                          \
            int dd = id >> 4, c = (id & 15) * 4;                              \
            cp_async16(base + (dd * FAS_STR + c) * 4,                         \
                       Kt + (size_t)dd * SEQ + (kt_) * 64 + c);               \
        }                                                                     \
        _Pragma("unroll")                                                     \
        for (int it = 0; it < 4; it++) {                                      \
            int id = tid + it * 256;                                          \
            int kk = id >> 5, c = (id & 31) * 4;                              \
            cp_async16(base + ((64 + kk) * FAS_STR + c) * 4,                  \
                       Vt + (size_t)((kt_) * 32 + kk) * 128 + c);             \
        }                                                                     \
        CP_COMMIT();                                                          \
    } while (0)

    FA_ISSUE(0, 0);

    // Q fragments: direct uint loads (pre-scaled half2 pairs along d)
    unsigned qf[8][4];
    {
        const unsigned* qh0 = g_qh + (size_t)(b * SEQ + qrow0) * 1024 + h * 64;
        const unsigned* qh1 = g_qh + (size_t)(b * SEQ + qrow1) * 1024 + h * 64;
#pragma unroll
        for (int ks = 0; ks < 8; ks++) {
            qf[ks][0] = qh0[ks * 8 + t];
            qf[ks][1] = qh1[ks * 8 + t];
            qf[ks][2] = qh0[ks * 8 + t + 4];
            qf[ks][3] = qh1[ks * 8 + t + 4];
        }
    }

    float of[16][4];
#pragma unroll
    for (int j = 0; j < 16; j++)
#pragma unroll
        for (int c = 0; c < 4; c++) of[j][c] = 0.0f;
    float m0 = -1e30f, m1 = -1e30f, l0 = 0.0f, l1 = 0.0f;

    for (int kt = 0; kt < nkt; kt++) {
        int k0 = kt * 64;
        int buf = kt & 1;

        CP_WAIT(0);
        __syncthreads();

        if (kt + 1 < nkt) FA_ISSUE(kt + 1, buf ^ 1);

        // fully-masked warps skip compute
        if (k0 > q0 + w * 16 + 15) continue;

        unsigned* Ks = smu + buf * FA_BUF;
        unsigned* Vs = Ks + 64 * FAS_STR;

        // --- S = Q @ K^T ---
        float sf[8][4];
#pragma unroll
        for (int j = 0; j < 8; j++)
#pragma unroll
            for (int c = 0; c < 4; c++) sf[j][c] = 0.0f;

#pragma unroll
        for (int ks = 0; ks < 8; ks++) {
#pragma unroll
            for (int j = 0; j < 8; j++) {
                unsigned b0 = Ks[(ks * 8 + t) * FAS_STR + j * 8 + g];
                unsigned b1 = Ks[(ks * 8 + t + 4) * FAS_STR + j * 8 + g];
                mma_f16(sf[j], qf[ks], b0, b1);
            }
        }

        if (kt >= nkt - 2) {
#pragma unroll
            for (int j = 0; j < 8; j++) {
                int kg0 = k0 + j * 8 + 2 * t;
                if (kg0 > qrow0)     sf[j][0] = -1e30f;
                if (kg0 + 1 > qrow0) sf[j][1] = -1e30f;
                if (kg0 > qrow1)     sf[j][2] = -1e30f;
                if (kg0 + 1 > qrow1) sf[j][3] = -1e30f;
            }
        }

        // --- online softmax ---
        float mt0 = -1e30f, mt1 = -1e30f;
#pragma unroll
        for (int j = 0; j < 8; j++) {
            mt0 = fmaxf(mt0, fmaxf(sf[j][0], sf[j][1]));
            mt1 = fmaxf(mt1, fmaxf(sf[j][2], sf[j][3]));
        }
        mt0 = fmaxf(mt0, __shfl_xor_sync(0xffffffffu, mt0, 1));
        mt0 = fmaxf(mt0, __shfl_xor_sync(0xffffffffu, mt0, 2));
        mt1 = fmaxf(mt1, __shfl_xor_sync(0xffffffffu, mt1, 1));
        mt1 = fmaxf(mt1, __shfl_xor_sync(0xffffffffu, mt1, 2));

        float mn0 = fmaxf(m0, mt0), mn1 = fmaxf(m1, mt1);
        float corr0 = __expf(m0 - mn0), corr1 = __expf(m1 - mn1);
        m0 = mn0; m1 = mn1;

        float rs0 = 0.0f, rs1 = 0.0f;
#pragma unroll
        for (int j = 0; j < 8; j++) {
            sf[j][0] = __expf(sf[j][0] - mn0);
            sf[j][1] = __expf(sf[j][1] - mn0);
            sf[j][2] = __expf(sf[j][2] - mn1);
            sf[j][3] = __expf(sf[j][3] - mn1);
            rs0 += sf[j][0] + sf[j][1];
            rs1 += sf[j][2] + sf[j][3];
        }
        rs0 += __shfl_xor_sync(0xffffffffu, rs0, 1);
        rs0 += __shfl_xor_sync(0xffffffffu, rs0, 2);
        rs1 += __shfl_xor_sync(0xffffffffu, rs1, 1);
        rs1 += __shfl_xor_sync(0xffffffffu, rs1, 2);
        l0 = l0 * corr0 + rs0;
        l1 = l1 * corr1 + rs1;

#pragma unroll
        for (int j = 0; j < 16; j++) {
            of[j][0] *= corr0; of[j][1] *= corr0;
            of[j][2] *= corr1; of[j][3] *= corr1;
        }

        // --- P fragments directly from softmax registers ---
        unsigned pf[4][4];
#pragma unroll
        for (int ks = 0; ks < 4; ks++) {
            pf[ks][0] = pack_h2(sf[2 * ks][0],     sf[2 * ks][1]);
            pf[ks][1] = pack_h2(sf[2 * ks][2],     sf[2 * ks][3]);
            pf[ks][2] = pack_h2(sf[2 * ks + 1][0], sf[2 * ks + 1][1]);
            pf[ks][3] = pack_h2(sf[2 * ks + 1][2], sf[2 * ks + 1][3]);
        }

        // --- O += P @ V ---
#pragma unroll
        for (int ks = 0; ks < 4; ks++) {
#pragma unroll
            for (int j = 0; j < 16; j++) {
                unsigned b0 = Vs[(ks * 8 + t) * FAS_STR + j * 8 + g];
                unsigned b1 = Vs[(ks * 8 + t + 4) * FAS_STR + j * 8 + g];
                mma_f16(of[j], pf[ks], b0, b1);
            }
        }
    }
#undef FA_ISSUE

    // epilogue: write O as half2 pairs-along-d (wo A layout)
    float inv0 = 1.0f / l0, inv1 = 1.0f / l1;
    unsigned* og0 = g_oh + (size_t)(b * SEQ + qrow0) * 1024 + h * 64;
    unsigned* og1 = g_oh + (size_t)(b * SEQ + qrow1) * 1024 + h * 64;
#pragma unroll
    for (int j = 0; j < 16; j++) {
        og0[j * 4 + t] = pack_h2(of[j][0] * inv0, of[j][1] * inv0);
        og1[j * 4 + t] = pack_h2(of[j][2] * inv1, of[j][3] * inv1);
    }
}

// ---------------------------------------------------------------------------
// Launch
// ---------------------------------------------------------------------------
extern "C" void kernel_launch(void* const* d_in, const int* in_sizes, int n_in,
                              void* d_out, int out_size)
{
    const float* x  = (const float*)d_in[0];
    const float* Wq = (const float*)d_in[1];
    const float* Wk = (const float*)d_in[2];
    const float* Wv = (const float*)d_in[3];
    const float* Wo = (const float*)d_in[4];
    const float* qw = (const float*)d_in[5];
    const float* kw = (const float*)d_in[6];
    float* out = (float*)d_out;

    cudaFuncSetAttribute(qkv_h_kernel,
                         cudaFuncAttributeMaxDynamicSharedMemorySize, GEMM_SMEM);
    cudaFuncSetAttribute(wo_h_kernel,
                         cudaFuncAttributeMaxDynamicSharedMemorySize, GEMM_SMEM);
    cudaFuncSetAttribute(flash_h_kernel,
                         cudaFuncAttributeMaxDynamicSharedMemorySize, FA_SMEM);

    // prep: rope table, pack x, pack weights
    rope_table_kernel<<<SEQ, 64>>>();
    pack_x_kernel<<<(TOKENS * 512) / 256, 256>>>(x);
    pack_w_kernel<<<(3145728 + 255) / 256, 256>>>(Wq, Wk, Wv, Wo);

    // fused QKV projection + RMSNorm + RoPE -> half layouts
    qkv_h_kernel<<<dim3(32, TOKENS / 128), 256, GEMM_SMEM>>>(qw, kw);

    // flash attention
    flash_h_kernel<<<dim3(SEQ / 128, NQ, BATCH), 256, FA_SMEM>>>();

    // output projection
    wo_h_kernel<<<dim3(HIDDEN / 128, TOKENS / 128), 256, GEMM_SMEM>>>(out);
}